// round 3
// baseline (speedup 1.0000x reference)
#include <cuda_runtime.h>

#define B 64
#define C 128
#define H 32
#define W 32
#define HW 1024
#define OUTC 640
#define WS_STRIDE 132  // padded oc-stride for 1x1 weight smem (bank-conflict relief, 16B aligned)

// ---------------- device scratch (allocation-free rule: __device__ globals) ---------------
__device__ float g_s0[B * C * HW];                 // 32 MB  preprocess0 output
__device__ float g_s1[B * C * HW];                 // 32 MB  preprocess1 output
__device__ float g_alpha[8][5];                    // softmaxed alphas
__device__ float g_wcomb[8 * C * 18 * C];          // [edge][ic][tap(0..8 conv,9..17 dil)][oc], pre-scaled

// ---------------- softmax over alpha rows ----------------
__global__ void softmax_kernel(const float* __restrict__ alphas) {
    int r = threadIdx.x;
    if (r < 8) {
        float m = -3.4e38f;
        #pragma unroll
        for (int j = 0; j < 5; j++) m = fmaxf(m, alphas[r * 5 + j]);
        float e[5], s = 0.f;
        #pragma unroll
        for (int j = 0; j < 5; j++) { e[j] = expf(alphas[r * 5 + j] - m); s += e[j]; }
        float inv = 1.f / s;
        #pragma unroll
        for (int j = 0; j < 5; j++) g_alpha[r][j] = e[j] * inv;
    }
}

// ---------------- weight transpose + alpha pre-scale ----------------
// g_wcomb[((e*C+ic)*18 + tap)*C + oc] = tap<9 ? a[e][1]*wc[e][oc][ic][tap]
//                                             : a[e][2]*wd[e][oc][ic][tap-9]
__global__ void prep_w_kernel(const float* __restrict__ wc, const float* __restrict__ wd) {
    int idx = blockIdx.x * blockDim.x + threadIdx.x;
    if (idx >= 8 * C * 18 * C) return;
    int oc = idx & 127;
    int rest = idx >> 7;
    int tap = rest % 18;
    int rest2 = rest / 18;
    int ic = rest2 & 127;
    int e = rest2 >> 7;
    float v;
    if (tap < 9) v = g_alpha[e][1] * wc[((e * C + oc) * C + ic) * 9 + tap];
    else         v = g_alpha[e][2] * wd[((e * C + oc) * C + ic) * 9 + (tap - 9)];
    g_wcomb[idx] = v;
}

// ---------------- 1x1 conv (preprocess): out[n][oc][p] = sum_ic w[oc][ic]*in[n][ic][p] ----------------
// grid 1024 (=64 batches x 16 pixel-chunks of 64), 256 threads, dynamic smem
__global__ __launch_bounds__(256) void conv1x1_kernel(const float* __restrict__ in,
                                                      const float* __restrict__ w,
                                                      float* __restrict__ out) {
    extern __shared__ float sm[];
    float* ws = sm;                    // [ic][oc] stride WS_STRIDE  (transposed)
    float* ins = sm + C * WS_STRIDE;   // [ic][64 px]
    int t = threadIdx.x;
    int n = blockIdx.x >> 4;
    int hw0 = (blockIdx.x & 15) << 6;

    for (int i = t; i < C * C; i += 256) {
        int oc = i >> 7, ic = i & 127;           // coalesced global read
        ws[ic * WS_STRIDE + oc] = w[i];          // (oc=i>>7 constant per warp chunk)
    }
    const float4* inb = (const float4*)(in + (long)n * C * HW + hw0);
    float4* insv = (float4*)ins;
    for (int i = t; i < C * 16; i += 256) {      // 16 float4 per ic row
        int ic = i >> 4, p4 = i & 15;
        insv[ic * 16 + p4] = inb[ic * (HW / 4) + p4];
    }
    __syncthreads();

    int pg = t & 15, og = t >> 4;
    int ocb = og * 8;
    float acc[4][8];
    #pragma unroll
    for (int k = 0; k < 4; k++)
        #pragma unroll
        for (int j = 0; j < 8; j++) acc[k][j] = 0.f;

    for (int ic = 0; ic < C; ic++) {
        float4 iv = *(const float4*)&ins[ic * 64 + pg * 4];
        float4 wa = *(const float4*)&ws[ic * WS_STRIDE + ocb];
        float4 wb = *(const float4*)&ws[ic * WS_STRIDE + ocb + 4];
        float xv[4] = {iv.x, iv.y, iv.z, iv.w};
        float wv[8] = {wa.x, wa.y, wa.z, wa.w, wb.x, wb.y, wb.z, wb.w};
        #pragma unroll
        for (int k = 0; k < 4; k++)
            #pragma unroll
            for (int j = 0; j < 8; j++) acc[k][j] += xv[k] * wv[j];
    }

    float* ob = out + (long)n * C * HW + hw0 + pg * 4;
    #pragma unroll
    for (int j = 0; j < 8; j++) {
        float4 o = make_float4(acc[0][j], acc[1][j], acc[2][j], acc[3][j]);
        *(float4*)&ob[(ocb + j) * HW] = o;
    }
}

// ---------------- fused node kernel ----------------
// s_out = a0(e0)*h0 + conv(h0, a1*Wc_e0) + dil(h0, a2*Wd_e0) + a3(e0)*avg(h0) + a4(e0)*max(h0)
//        + same for (h1, e1)
// grid (16 tiles, 64 batch), 256 threads. Tile 8x8 px, all 128 oc.
__global__ __launch_bounds__(256) void node_kernel(const float* __restrict__ h0, int h0_bs,
                                                   const float* __restrict__ h1, int h1_bs,
                                                   int e0, int e1,
                                                   float* __restrict__ out) {
    __shared__ float in_t[12 * 12];
    __shared__ float ws[18 * 128];

    int t = threadIdx.x;
    int pg = t & 15, og = t >> 4;
    int r = pg >> 1, cb = (pg & 1) * 4;
    int ocb = og * 8;
    int b = blockIdx.y;
    int tile = blockIdx.x;
    int y0 = (tile >> 2) * 8, x0 = (tile & 3) * 8;

    float acc[4][8];
    #pragma unroll
    for (int k = 0; k < 4; k++)
        #pragma unroll
        for (int j = 0; j < 8; j++) acc[k][j] = 0.f;

    float a0A = g_alpha[e0][0], a3A = g_alpha[e0][3] * (1.f / 9.f), a4A = g_alpha[e0][4];
    float a0B = g_alpha[e1][0], a3B = g_alpha[e1][3] * (1.f / 9.f), a4B = g_alpha[e1][4];

    const float* hb0 = h0 + (long)b * h0_bs;
    const float* hb1 = h1 + (long)b * h1_bs;

    for (int ic = 0; ic < 2 * C; ic++) {
        int ch = ic & 127;
        const float* hb = (ic < C) ? hb0 : hb1;
        int e = (ic < C) ? e0 : e1;

        __syncthreads();
        if (t < 144) {
            int rr = t / 12, cc = t - rr * 12;
            int gy = y0 + rr - 2, gx = x0 + cc - 2;
            float v = 0.f;
            if ((unsigned)gy < 32u && (unsigned)gx < 32u) v = hb[ch * HW + (gy << 5) + gx];
            in_t[rr * 12 + cc] = v;
        }
        const float* wsrc = g_wcomb + (long)(e * C + ch) * 18 * C;
        #pragma unroll
        for (int j = 0; j < 9; j++) ws[t + j * 256] = wsrc[t + j * 256];
        __syncthreads();

        // stage 5 rows x 8 cols from the tile into registers (16B-aligned: 12*row + cb)
        float iv[5][8];
        #pragma unroll
        for (int dy = 0; dy < 5; dy++) {
            float4 va = *(const float4*)&in_t[(r + dy) * 12 + cb];
            float4 vb = *(const float4*)&in_t[(r + dy) * 12 + cb + 4];
            iv[dy][0] = va.x; iv[dy][1] = va.y; iv[dy][2] = va.z; iv[dy][3] = va.w;
            iv[dy][4] = vb.x; iv[dy][5] = vb.y; iv[dy][6] = vb.z; iv[dy][7] = vb.w;
        }

        #pragma unroll
        for (int ty = 0; ty < 3; ty++) {
            #pragma unroll
            for (int tx = 0; tx < 3; tx++) {
                int tap = ty * 3 + tx;
                float4 wa = *(const float4*)&ws[tap * 128 + ocb];
                float4 wb = *(const float4*)&ws[tap * 128 + ocb + 4];
                #pragma unroll
                for (int k = 0; k < 4; k++) {
                    float x = iv[ty + 1][tx + 1 + k];
                    acc[k][0] += x * wa.x; acc[k][1] += x * wa.y;
                    acc[k][2] += x * wa.z; acc[k][3] += x * wa.w;
                    acc[k][4] += x * wb.x; acc[k][5] += x * wb.y;
                    acc[k][6] += x * wb.z; acc[k][7] += x * wb.w;
                }
                float4 da = *(const float4*)&ws[(9 + tap) * 128 + ocb];
                float4 db = *(const float4*)&ws[(9 + tap) * 128 + ocb + 4];
                #pragma unroll
                for (int k = 0; k < 4; k++) {
                    float x = iv[ty * 2][tx * 2 + k];
                    acc[k][0] += x * da.x; acc[k][1] += x * da.y;
                    acc[k][2] += x * da.z; acc[k][3] += x * da.w;
                    acc[k][4] += x * db.x; acc[k][5] += x * db.y;
                    acc[k][6] += x * db.z; acc[k][7] += x * db.w;
                }
            }
        }

        // identity + avg pool + max pool, only the thread group owning oc == ch
        if ((ch >> 3) == og) {
            float a0, a3, a4;
            if (ic < C) { a0 = a0A; a3 = a3A; a4 = a4A; }
            else        { a0 = a0B; a3 = a3B; a4 = a4B; }
            int l = ch & 7;
            #pragma unroll
            for (int k = 0; k < 4; k++) {
                float s9 = 0.f, m = -3.4e38f;
                #pragma unroll
                for (int dy = -1; dy <= 1; dy++) {
                    #pragma unroll
                    for (int dx = -1; dx <= 1; dx++) {
                        float val = iv[2 + dy][2 + dx + k];
                        s9 += val;   // zero-padded tile -> count_include_pad avg is correct
                        int gy = y0 + r + dy, gx = x0 + cb + k + dx;
                        if ((unsigned)gy < 32u && (unsigned)gx < 32u) m = fmaxf(m, val);
                    }
                }
                float p = a0 * iv[2][2 + k] + a3 * s9 + a4 * m;
                #pragma unroll
                for (int j = 0; j < 8; j++) if (j == l) acc[k][j] += p;
            }
        }
    }

    float* ob = out + (long)b * (OUTC * HW) + (y0 + r) * W + x0 + cb;
    #pragma unroll
    for (int j = 0; j < 8; j++) {
        float4 o = make_float4(acc[0][j], acc[1][j], acc[2][j], acc[3][j]);
        *(float4*)&ob[(ocb + j) * HW] = o;
    }
}

// ---------------- skip copies: out[:,512:640,:,:] = skip ; tuple tail = skip ----------------
__global__ void copy_skip_kernel(const float* __restrict__ skip, float* __restrict__ out) {
    int idx = blockIdx.x * blockDim.x + threadIdx.x;   // over B*C*HW/4 = 2097152 float4
    float4 v = ((const float4*)skip)[idx];
    int hw4 = idx & 255;
    int c = (idx >> 8) & 127;
    int n = idx >> 15;
    ((float4*)out)[(long)n * (OUTC * HW / 4) + (512 + c) * (HW / 4) + hw4] = v;
    ((float4*)out)[(long)B * OUTC * HW / 4 + idx] = v;
}

// ---------------- launch ----------------
extern "C" void kernel_launch(void* const* d_in, const int* in_sizes, int n_in,
                              void* d_out, int out_size) {
    const float* input0  = (const float*)d_in[0];
    const float* input1  = (const float*)d_in[1];
    const float* skip    = (const float*)d_in[2];
    const float* w_pre0  = (const float*)d_in[3];
    const float* w_pre1  = (const float*)d_in[4];
    const float* w_conv3 = (const float*)d_in[5];
    const float* w_dil3  = (const float*)d_in[6];
    const float* alphas  = (const float*)d_in[7];
    float* out = (float*)d_out;

    float *s0, *s1;
    cudaGetSymbolAddress((void**)&s0, g_s0);
    cudaGetSymbolAddress((void**)&s1, g_s1);

    softmax_kernel<<<1, 32>>>(alphas);
    prep_w_kernel<<<(8 * C * 18 * C) / 256, 256>>>(w_conv3, w_dil3);

    const int smem1x1 = (C * WS_STRIDE + C * 64) * sizeof(float);  // ~100 KB
    cudaFuncSetAttribute(conv1x1_kernel, cudaFuncAttributeMaxDynamicSharedMemorySize, smem1x1);
    conv1x1_kernel<<<1024, 256, smem1x1>>>(input0, w_pre0, s0);
    conv1x1_kernel<<<1024, 256, smem1x1>>>(input1, w_pre1, s1);

    dim3 ngrid(16, 64);
    // node 0: h0=s0, h1=s1 -> slice 0
    node_kernel<<<ngrid, 256>>>(s0, C * HW, s1, C * HW, 0, 1, out + 0 * C * HW);
    // node 1: h0=s1, h1=s2(slice0) -> slice 1
    node_kernel<<<ngrid, 256>>>(s1, C * HW, out + 0 * C * HW, OUTC * HW, 2, 3, out + 1 * C * HW);
    // node 2: h0=s2, h1=s3 -> slice 2
    node_kernel<<<ngrid, 256>>>(out + 0 * C * HW, OUTC * HW, out + 1 * C * HW, OUTC * HW, 4, 5,
                                out + 2 * C * HW);
    // node 3: h0=s3, h1=s4 -> slice 3
    node_kernel<<<ngrid, 256>>>(out + 1 * C * HW, OUTC * HW, out + 2 * C * HW, OUTC * HW, 6, 7,
                                out + 3 * C * HW);

    copy_skip_kernel<<<(B * C * HW / 4) / 256, 256>>>(skip, out);
}

// round 4
// speedup vs baseline: 1.5816x; 1.5816x over previous
#include <cuda_runtime.h>

#define B 64
#define C 128
#define H 32
#define W 32
#define HW 1024
#define OUTC 640
#define WS_STRIDE 132  // padded oc-stride for 1x1 weight smem (bank-conflict relief, 16B aligned)

// ---------------- device scratch (allocation-free rule: __device__ globals) ---------------
__device__ float g_s0[B * C * HW];                 // 32 MB  preprocess0 output
__device__ float g_s1[B * C * HW];                 // 32 MB  preprocess1 output
__device__ float g_alpha[8][5];                    // softmaxed alphas
__device__ float g_wcomb[8 * C * 18 * C];          // [edge][ic][tap(0..8 conv,9..17 dil)][oc], pre-scaled

// ---------------- softmax over alpha rows ----------------
__global__ void softmax_kernel(const float* __restrict__ alphas) {
    int r = threadIdx.x;
    if (r < 8) {
        float m = -3.4e38f;
        #pragma unroll
        for (int j = 0; j < 5; j++) m = fmaxf(m, alphas[r * 5 + j]);
        float e[5], s = 0.f;
        #pragma unroll
        for (int j = 0; j < 5; j++) { e[j] = expf(alphas[r * 5 + j] - m); s += e[j]; }
        float inv = 1.f / s;
        #pragma unroll
        for (int j = 0; j < 5; j++) g_alpha[r][j] = e[j] * inv;
    }
}

// ---------------- weight transpose + alpha pre-scale ----------------
// g_wcomb[((e*C+ic)*18 + tap)*C + oc] = tap<9 ? a[e][1]*wc[e][oc][ic][tap]
//                                             : a[e][2]*wd[e][oc][ic][tap-9]
__global__ void prep_w_kernel(const float* __restrict__ wc, const float* __restrict__ wd) {
    int idx = blockIdx.x * blockDim.x + threadIdx.x;
    if (idx >= 8 * C * 18 * C) return;
    int oc = idx & 127;
    int rest = idx >> 7;
    int tap = rest % 18;
    int rest2 = rest / 18;
    int ic = rest2 & 127;
    int e = rest2 >> 7;
    float v;
    if (tap < 9) v = g_alpha[e][1] * wc[((e * C + oc) * C + ic) * 9 + tap];
    else         v = g_alpha[e][2] * wd[((e * C + oc) * C + ic) * 9 + (tap - 9)];
    g_wcomb[idx] = v;
}

// ---------------- 1x1 conv (preprocess): out[n][oc][p] = sum_ic w[oc][ic]*in[n][ic][p] ----------------
// grid 1024 (=64 batches x 16 pixel-chunks of 64), 256 threads, dynamic smem
__global__ __launch_bounds__(256) void conv1x1_kernel(const float* __restrict__ in,
                                                      const float* __restrict__ w,
                                                      float* __restrict__ out) {
    extern __shared__ float sm[];
    float* ws = sm;                    // [ic][oc] stride WS_STRIDE  (transposed)
    float* ins = sm + C * WS_STRIDE;   // [ic][64 px]
    int t = threadIdx.x;
    int n = blockIdx.x >> 4;
    int hw0 = (blockIdx.x & 15) << 6;

    for (int i = t; i < C * C; i += 256) {
        int oc = i >> 7, ic = i & 127;           // coalesced global read
        ws[ic * WS_STRIDE + oc] = w[i];          // (oc=i>>7 constant per warp chunk)
    }
    const float4* inb = (const float4*)(in + (long)n * C * HW + hw0);
    float4* insv = (float4*)ins;
    for (int i = t; i < C * 16; i += 256) {      // 16 float4 per ic row
        int ic = i >> 4, p4 = i & 15;
        insv[ic * 16 + p4] = inb[ic * (HW / 4) + p4];
    }
    __syncthreads();

    int pg = t & 15, og = t >> 4;
    int ocb = og * 8;
    float acc[4][8];
    #pragma unroll
    for (int k = 0; k < 4; k++)
        #pragma unroll
        for (int j = 0; j < 8; j++) acc[k][j] = 0.f;

    for (int ic = 0; ic < C; ic++) {
        float4 iv = *(const float4*)&ins[ic * 64 + pg * 4];
        float4 wa = *(const float4*)&ws[ic * WS_STRIDE + ocb];
        float4 wb = *(const float4*)&ws[ic * WS_STRIDE + ocb + 4];
        float xv[4] = {iv.x, iv.y, iv.z, iv.w};
        float wv[8] = {wa.x, wa.y, wa.z, wa.w, wb.x, wb.y, wb.z, wb.w};
        #pragma unroll
        for (int k = 0; k < 4; k++)
            #pragma unroll
            for (int j = 0; j < 8; j++) acc[k][j] += xv[k] * wv[j];
    }

    float* ob = out + (long)n * C * HW + hw0 + pg * 4;
    #pragma unroll
    for (int j = 0; j < 8; j++) {
        float4 o = make_float4(acc[0][j], acc[1][j], acc[2][j], acc[3][j]);
        *(float4*)&ob[(ocb + j) * HW] = o;
    }
}

// ---------------- fused node kernel ----------------
// s_out = a0(e0)*h0 + conv(h0, a1*Wc_e0) + dil(h0, a2*Wd_e0) + a3(e0)*avg(h0) + a4(e0)*max(h0)
//        + same for (h1, e1)
// grid (16 tiles, 64 batch), 256 threads. Tile 8x8 px, all 128 oc.
__global__ __launch_bounds__(256) void node_kernel(const float* __restrict__ h0, int h0_bs,
                                                   const float* __restrict__ h1, int h1_bs,
                                                   int e0, int e1,
                                                   float* __restrict__ out) {
    __shared__ float in_t[12 * 12];
    __shared__ float ws[18 * 128];

    int t = threadIdx.x;
    int pg = t & 15, og = t >> 4;
    int r = pg >> 1, cb = (pg & 1) * 4;
    int ocb = og * 8;
    int b = blockIdx.y;
    int tile = blockIdx.x;
    int y0 = (tile >> 2) * 8, x0 = (tile & 3) * 8;

    float acc[4][8];
    #pragma unroll
    for (int k = 0; k < 4; k++)
        #pragma unroll
        for (int j = 0; j < 8; j++) acc[k][j] = 0.f;

    float a0A = g_alpha[e0][0], a3A = g_alpha[e0][3] * (1.f / 9.f), a4A = g_alpha[e0][4];
    float a0B = g_alpha[e1][0], a3B = g_alpha[e1][3] * (1.f / 9.f), a4B = g_alpha[e1][4];

    const float* hb0 = h0 + (long)b * h0_bs;
    const float* hb1 = h1 + (long)b * h1_bs;

    for (int ic = 0; ic < 2 * C; ic++) {
        int ch = ic & 127;
        const float* hb = (ic < C) ? hb0 : hb1;
        int e = (ic < C) ? e0 : e1;

        __syncthreads();
        if (t < 144) {
            int rr = t / 12, cc = t - rr * 12;
            int gy = y0 + rr - 2, gx = x0 + cc - 2;
            float v = 0.f;
            if ((unsigned)gy < 32u && (unsigned)gx < 32u) v = hb[ch * HW + (gy << 5) + gx];
            in_t[rr * 12 + cc] = v;
        }
        const float* wsrc = g_wcomb + (long)(e * C + ch) * 18 * C;
        #pragma unroll
        for (int j = 0; j < 9; j++) ws[t + j * 256] = wsrc[t + j * 256];
        __syncthreads();

        // stage 5 rows x 8 cols from the tile into registers (16B-aligned: 12*row + cb)
        float iv[5][8];
        #pragma unroll
        for (int dy = 0; dy < 5; dy++) {
            float4 va = *(const float4*)&in_t[(r + dy) * 12 + cb];
            float4 vb = *(const float4*)&in_t[(r + dy) * 12 + cb + 4];
            iv[dy][0] = va.x; iv[dy][1] = va.y; iv[dy][2] = va.z; iv[dy][3] = va.w;
            iv[dy][4] = vb.x; iv[dy][5] = vb.y; iv[dy][6] = vb.z; iv[dy][7] = vb.w;
        }

        #pragma unroll
        for (int ty = 0; ty < 3; ty++) {
            #pragma unroll
            for (int tx = 0; tx < 3; tx++) {
                int tap = ty * 3 + tx;
                float4 wa = *(const float4*)&ws[tap * 128 + ocb];
                float4 wb = *(const float4*)&ws[tap * 128 + ocb + 4];
                #pragma unroll
                for (int k = 0; k < 4; k++) {
                    float x = iv[ty + 1][tx + 1 + k];
                    acc[k][0] += x * wa.x; acc[k][1] += x * wa.y;
                    acc[k][2] += x * wa.z; acc[k][3] += x * wa.w;
                    acc[k][4] += x * wb.x; acc[k][5] += x * wb.y;
                    acc[k][6] += x * wb.z; acc[k][7] += x * wb.w;
                }
                float4 da = *(const float4*)&ws[(9 + tap) * 128 + ocb];
                float4 db = *(const float4*)&ws[(9 + tap) * 128 + ocb + 4];
                #pragma unroll
                for (int k = 0; k < 4; k++) {
                    float x = iv[ty * 2][tx * 2 + k];
                    acc[k][0] += x * da.x; acc[k][1] += x * da.y;
                    acc[k][2] += x * da.z; acc[k][3] += x * da.w;
                    acc[k][4] += x * db.x; acc[k][5] += x * db.y;
                    acc[k][6] += x * db.z; acc[k][7] += x * db.w;
                }
            }
        }

        // identity + avg pool + max pool, only the thread group owning oc == ch
        if ((ch >> 3) == og) {
            float a0, a3, a4;
            if (ic < C) { a0 = a0A; a3 = a3A; a4 = a4A; }
            else        { a0 = a0B; a3 = a3B; a4 = a4B; }
            int l = ch & 7;
            #pragma unroll
            for (int k = 0; k < 4; k++) {
                float s9 = 0.f, m = -3.4e38f;
                #pragma unroll
                for (int dy = -1; dy <= 1; dy++) {
                    #pragma unroll
                    for (int dx = -1; dx <= 1; dx++) {
                        float val = iv[2 + dy][2 + dx + k];
                        s9 += val;   // zero-padded tile -> count_include_pad avg is correct
                        int gy = y0 + r + dy, gx = x0 + cb + k + dx;
                        if ((unsigned)gy < 32u && (unsigned)gx < 32u) m = fmaxf(m, val);
                    }
                }
                float p = a0 * iv[2][2 + k] + a3 * s9 + a4 * m;
                #pragma unroll
                for (int j = 0; j < 8; j++) if (j == l) acc[k][j] += p;
            }
        }
    }

    float* ob = out + (long)b * (OUTC * HW) + (y0 + r) * W + x0 + cb;
    #pragma unroll
    for (int j = 0; j < 8; j++) {
        float4 o = make_float4(acc[0][j], acc[1][j], acc[2][j], acc[3][j]);
        *(float4*)&ob[(ocb + j) * HW] = o;
    }
}

// ---------------- skip copies: out[:,512:640,:,:] = skip ; tuple tail = skip ----------------
__global__ void copy_skip_kernel(const float* __restrict__ skip, float* __restrict__ out) {
    int idx = blockIdx.x * blockDim.x + threadIdx.x;   // over B*C*HW/4 = 2097152 float4
    float4 v = ((const float4*)skip)[idx];
    int hw4 = idx & 255;
    int c = (idx >> 8) & 127;
    int n = idx >> 15;
    ((float4*)out)[(long)n * (OUTC * HW / 4) + (512 + c) * (HW / 4) + hw4] = v;
    ((float4*)out)[(long)B * OUTC * HW / 4 + idx] = v;
}

// ---------------- launch ----------------
extern "C" void kernel_launch(void* const* d_in, const int* in_sizes, int n_in,
                              void* d_out, int out_size) {
    const float* input0  = (const float*)d_in[0];
    const float* input1  = (const float*)d_in[1];
    const float* skip    = (const float*)d_in[2];
    const float* w_pre0  = (const float*)d_in[3];
    const float* w_pre1  = (const float*)d_in[4];
    const float* w_conv3 = (const float*)d_in[5];
    const float* w_dil3  = (const float*)d_in[6];
    const float* alphas  = (const float*)d_in[7];
    float* out = (float*)d_out;

    float *s0, *s1;
    cudaGetSymbolAddress((void**)&s0, g_s0);
    cudaGetSymbolAddress((void**)&s1, g_s1);

    softmax_kernel<<<1, 32>>>(alphas);
    prep_w_kernel<<<(8 * C * 18 * C) / 256, 256>>>(w_conv3, w_dil3);

    const int smem1x1 = (C * WS_STRIDE + C * 64) * sizeof(float);  // ~100 KB
    cudaFuncSetAttribute(conv1x1_kernel, cudaFuncAttributeMaxDynamicSharedMemorySize, smem1x1);
    conv1x1_kernel<<<1024, 256, smem1x1>>>(input0, w_pre0, s0);
    conv1x1_kernel<<<1024, 256, smem1x1>>>(input1, w_pre1, s1);

    dim3 ngrid(16, 64);
    // node 0: h0=s0, h1=s1 -> slice 0
    node_kernel<<<ngrid, 256>>>(s0, C * HW, s1, C * HW, 0, 1, out + 0 * C * HW);
    // node 1: h0=s1, h1=s2(slice0) -> slice 1
    node_kernel<<<ngrid, 256>>>(s1, C * HW, out + 0 * C * HW, OUTC * HW, 2, 3, out + 1 * C * HW);
    // node 2: h0=s2, h1=s3 -> slice 2
    node_kernel<<<ngrid, 256>>>(out + 0 * C * HW, OUTC * HW, out + 1 * C * HW, OUTC * HW, 4, 5,
                                out + 2 * C * HW);
    // node 3: h0=s3, h1=s4 -> slice 3
    node_kernel<<<ngrid, 256>>>(out + 1 * C * HW, OUTC * HW, out + 2 * C * HW, OUTC * HW, 6, 7,
                                out + 3 * C * HW);

    copy_skip_kernel<<<(B * C * HW / 4) / 256, 256>>>(skip, out);
}

// round 5
// speedup vs baseline: 1.6410x; 1.0376x over previous
#include <cuda_runtime.h>

#define B 64
#define C 128
#define H 32
#define W 32
#define HW 1024
#define OUTC 640
#define WS_STRIDE 132

typedef unsigned long long u64;

// ---- packed fp32x2 helpers (Blackwell FFMA2 — ptxas never emits this from C++) ----
__device__ __forceinline__ u64 pk2(float lo, float hi) {
    u64 r;
    asm("mov.b64 %0, {%1, %2};" : "=l"(r) : "f"(lo), "f"(hi));
    return r;
}
__device__ __forceinline__ void ffma2(u64& d, u64 a, u64 b) {
    asm("fma.rn.f32x2 %0, %1, %2, %0;" : "+l"(d) : "l"(a), "l"(b));
}
__device__ __forceinline__ void fadd2(u64& d, u64 a) {
    asm("add.rn.f32x2 %0, %0, %1;" : "+l"(d) : "l"(a));
}
__device__ __forceinline__ float2 upk(u64 v) {
    float2 r;
    asm("mov.b64 {%0, %1}, %2;" : "=f"(r.x), "=f"(r.y) : "l"(v));
    return r;
}

// ---------------- device scratch ---------------
__device__ float g_s0[B * C * HW];
__device__ float g_s1[B * C * HW];
__device__ float g_alpha[8][5];
__device__ float g_wcomb[8 * C * 18 * C];   // [edge][ic][tap(0..8 conv,9..17 dil)][oc], alpha-scaled

// ---------------- softmax over alpha rows ----------------
__global__ void softmax_kernel(const float* __restrict__ alphas) {
    int r = threadIdx.x;
    if (r < 8) {
        float m = -3.4e38f;
        #pragma unroll
        for (int j = 0; j < 5; j++) m = fmaxf(m, alphas[r * 5 + j]);
        float e[5], s = 0.f;
        #pragma unroll
        for (int j = 0; j < 5; j++) { e[j] = expf(alphas[r * 5 + j] - m); s += e[j]; }
        float inv = 1.f / s;
        #pragma unroll
        for (int j = 0; j < 5; j++) g_alpha[r][j] = e[j] * inv;
    }
}

// ---------------- weight transpose + alpha pre-scale ----------------
__global__ void prep_w_kernel(const float* __restrict__ wc, const float* __restrict__ wd) {
    int idx = blockIdx.x * blockDim.x + threadIdx.x;
    if (idx >= 8 * C * 18 * C) return;
    int oc = idx & 127;
    int rest = idx >> 7;
    int tap = rest % 18;
    int rest2 = rest / 18;
    int ic = rest2 & 127;
    int e = rest2 >> 7;
    float v;
    if (tap < 9) v = g_alpha[e][1] * wc[((e * C + oc) * C + ic) * 9 + tap];
    else         v = g_alpha[e][2] * wd[((e * C + oc) * C + ic) * 9 + (tap - 9)];
    g_wcomb[idx] = v;
}

// ---------------- 1x1 conv (preprocess) with packed FFMA2 ----------------
__global__ __launch_bounds__(256) void conv1x1_kernel(const float* __restrict__ in,
                                                      const float* __restrict__ w,
                                                      float* __restrict__ out) {
    extern __shared__ float sm[];
    float* ws = sm;                    // [ic][oc] stride WS_STRIDE (transposed)
    float* ins = sm + C * WS_STRIDE;   // [ic][64 px]
    int t = threadIdx.x;
    int n = blockIdx.x >> 4;
    int hw0 = (blockIdx.x & 15) << 6;

    for (int i = t; i < C * C; i += 256) {
        int oc = i >> 7, ic = i & 127;
        ws[ic * WS_STRIDE + oc] = w[i];
    }
    const float4* inb = (const float4*)(in + (long)n * C * HW + hw0);
    float4* insv = (float4*)ins;
    for (int i = t; i < C * 16; i += 256) {
        int ic = i >> 4, p4 = i & 15;
        insv[ic * 16 + p4] = inb[ic * (HW / 4) + p4];
    }
    __syncthreads();

    int pg = t & 15, og = t >> 4;
    int ocb = og * 8;
    u64 acc2[4][4];
    #pragma unroll
    for (int k = 0; k < 4; k++)
        #pragma unroll
        for (int j = 0; j < 4; j++) acc2[k][j] = 0ull;

    for (int ic = 0; ic < C; ic++) {
        float4 iv = *(const float4*)&ins[ic * 64 + pg * 4];
        float4 wa = *(const float4*)&ws[ic * WS_STRIDE + ocb];
        float4 wb = *(const float4*)&ws[ic * WS_STRIDE + ocb + 4];
        u64 w0 = pk2(wa.x, wa.y), w1 = pk2(wa.z, wa.w);
        u64 w2 = pk2(wb.x, wb.y), w3 = pk2(wb.z, wb.w);
        float xv[4] = {iv.x, iv.y, iv.z, iv.w};
        #pragma unroll
        for (int k = 0; k < 4; k++) {
            u64 xd = pk2(xv[k], xv[k]);
            ffma2(acc2[k][0], xd, w0);
            ffma2(acc2[k][1], xd, w1);
            ffma2(acc2[k][2], xd, w2);
            ffma2(acc2[k][3], xd, w3);
        }
    }

    float* ob = out + (long)n * C * HW + hw0 + pg * 4;
    #pragma unroll
    for (int jp = 0; jp < 4; jp++) {
        float2 v0 = upk(acc2[0][jp]), v1 = upk(acc2[1][jp]);
        float2 v2 = upk(acc2[2][jp]), v3 = upk(acc2[3][jp]);
        *(float4*)&ob[(ocb + 2 * jp) * HW]     = make_float4(v0.x, v1.x, v2.x, v3.x);
        *(float4*)&ob[(ocb + 2 * jp + 1) * HW] = make_float4(v0.y, v1.y, v2.y, v3.y);
    }
}

// ---------------- fused node kernel (packed FFMA2 mainloop) ----------------
__global__ __launch_bounds__(256) void node_kernel(const float* __restrict__ h0, int h0_bs,
                                                   const float* __restrict__ h1, int h1_bs,
                                                   int e0, int e1,
                                                   float* __restrict__ out) {
    __shared__ float in_t[12 * 12];
    __shared__ float ws[18 * 128];

    int t = threadIdx.x;
    int pg = t & 15, og = t >> 4;
    int r = pg >> 1, cb = (pg & 1) * 4;
    int ocb = og * 8;
    int b = blockIdx.y;
    int tile = blockIdx.x;
    int y0 = (tile >> 2) * 8, x0 = (tile & 3) * 8;

    u64 acc2[4][4];     // [pixel k][oc pair]
    #pragma unroll
    for (int k = 0; k < 4; k++)
        #pragma unroll
        for (int j = 0; j < 4; j++) acc2[k][j] = 0ull;

    float a0A = g_alpha[e0][0], a3A = g_alpha[e0][3] * (1.f / 9.f), a4A = g_alpha[e0][4];
    float a0B = g_alpha[e1][0], a3B = g_alpha[e1][3] * (1.f / 9.f), a4B = g_alpha[e1][4];

    const float* hb0 = h0 + (long)b * h0_bs;
    const float* hb1 = h1 + (long)b * h1_bs;

    for (int ic = 0; ic < 2 * C; ic++) {
        int ch = ic & 127;
        const float* hb = (ic < C) ? hb0 : hb1;
        int e = (ic < C) ? e0 : e1;

        __syncthreads();
        if (t < 144) {
            int rr = t / 12, cc = t - rr * 12;
            int gy = y0 + rr - 2, gx = x0 + cc - 2;
            float v = 0.f;
            if ((unsigned)gy < 32u && (unsigned)gx < 32u) v = hb[ch * HW + (gy << 5) + gx];
            in_t[rr * 12 + cc] = v;
        }
        const float* wsrc = g_wcomb + (long)(e * C + ch) * 18 * C;
        #pragma unroll
        for (int j = 0; j < 9; j++) ws[t + j * 256] = wsrc[t + j * 256];
        __syncthreads();

        // stage 5 rows x 8 cols into registers
        float iv[5][8];
        #pragma unroll
        for (int dy = 0; dy < 5; dy++) {
            float4 va = *(const float4*)&in_t[(r + dy) * 12 + cb];
            float4 vb = *(const float4*)&in_t[(r + dy) * 12 + cb + 4];
            iv[dy][0] = va.x; iv[dy][1] = va.y; iv[dy][2] = va.z; iv[dy][3] = va.w;
            iv[dy][4] = vb.x; iv[dy][5] = vb.y; iv[dy][6] = vb.z; iv[dy][7] = vb.w;
        }

        #pragma unroll
        for (int ty = 0; ty < 3; ty++) {
            #pragma unroll
            for (int tx = 0; tx < 3; tx++) {
                int tap = ty * 3 + tx;
                // regular conv taps
                {
                    float4 wa = *(const float4*)&ws[tap * 128 + ocb];
                    float4 wb = *(const float4*)&ws[tap * 128 + ocb + 4];
                    u64 w0 = pk2(wa.x, wa.y), w1 = pk2(wa.z, wa.w);
                    u64 w2 = pk2(wb.x, wb.y), w3 = pk2(wb.z, wb.w);
                    #pragma unroll
                    for (int k = 0; k < 4; k++) {
                        float x = iv[ty + 1][tx + 1 + k];
                        u64 xd = pk2(x, x);
                        ffma2(acc2[k][0], xd, w0);
                        ffma2(acc2[k][1], xd, w1);
                        ffma2(acc2[k][2], xd, w2);
                        ffma2(acc2[k][3], xd, w3);
                    }
                }
                // dilated conv taps
                {
                    float4 da = *(const float4*)&ws[(9 + tap) * 128 + ocb];
                    float4 db = *(const float4*)&ws[(9 + tap) * 128 + ocb + 4];
                    u64 d0 = pk2(da.x, da.y), d1 = pk2(da.z, da.w);
                    u64 d2 = pk2(db.x, db.y), d3 = pk2(db.z, db.w);
                    #pragma unroll
                    for (int k = 0; k < 4; k++) {
                        float x = iv[ty * 2][tx * 2 + k];
                        u64 xd = pk2(x, x);
                        ffma2(acc2[k][0], xd, d0);
                        ffma2(acc2[k][1], xd, d1);
                        ffma2(acc2[k][2], xd, d2);
                        ffma2(acc2[k][3], xd, d3);
                    }
                }
            }
        }

        // identity + avg pool + max pool: thread group owning oc == ch adds pooled terms
        if ((ch >> 3) == og) {
            float a0, a3, a4;
            if (ic < C) { a0 = a0A; a3 = a3A; a4 = a4A; }
            else        { a0 = a0B; a3 = a3B; a4 = a4B; }
            int l = ch & 7;
            #pragma unroll
            for (int k = 0; k < 4; k++) {
                float s9 = 0.f, m = -3.4e38f;
                #pragma unroll
                for (int dy = -1; dy <= 1; dy++) {
                    #pragma unroll
                    for (int dx = -1; dx <= 1; dx++) {
                        float val = iv[2 + dy][2 + dx + k];
                        s9 += val;   // zero-padded tile -> count_include_pad avg correct
                        int gy = y0 + r + dy, gx = x0 + cb + k + dx;
                        if ((unsigned)gy < 32u && (unsigned)gx < 32u) m = fmaxf(m, val);
                    }
                }
                float p = a0 * iv[2][2 + k] + a3 * s9 + a4 * m;
                u64 pp = (l & 1) ? pk2(0.f, p) : pk2(p, 0.f);
                fadd2(acc2[k][l >> 1], pp);
            }
        }
    }

    float* ob = out + (long)b * (OUTC * HW) + (y0 + r) * W + x0 + cb;
    #pragma unroll
    for (int jp = 0; jp < 4; jp++) {
        float2 v0 = upk(acc2[0][jp]), v1 = upk(acc2[1][jp]);
        float2 v2 = upk(acc2[2][jp]), v3 = upk(acc2[3][jp]);
        *(float4*)&ob[(ocb + 2 * jp) * HW]     = make_float4(v0.x, v1.x, v2.x, v3.x);
        *(float4*)&ob[(ocb + 2 * jp + 1) * HW] = make_float4(v0.y, v1.y, v2.y, v3.y);
    }
}

// ---------------- skip copies ----------------
__global__ void copy_skip_kernel(const float* __restrict__ skip, float* __restrict__ out) {
    int idx = blockIdx.x * blockDim.x + threadIdx.x;
    float4 v = ((const float4*)skip)[idx];
    int hw4 = idx & 255;
    int c = (idx >> 8) & 127;
    int n = idx >> 15;
    ((float4*)out)[(long)n * (OUTC * HW / 4) + (512 + c) * (HW / 4) + hw4] = v;
    ((float4*)out)[(long)B * OUTC * HW / 4 + idx] = v;
}

// ---------------- launch ----------------
extern "C" void kernel_launch(void* const* d_in, const int* in_sizes, int n_in,
                              void* d_out, int out_size) {
    const float* input0  = (const float*)d_in[0];
    const float* input1  = (const float*)d_in[1];
    const float* skip    = (const float*)d_in[2];
    const float* w_pre0  = (const float*)d_in[3];
    const float* w_pre1  = (const float*)d_in[4];
    const float* w_conv3 = (const float*)d_in[5];
    const float* w_dil3  = (const float*)d_in[6];
    const float* alphas  = (const float*)d_in[7];
    float* out = (float*)d_out;

    float *s0, *s1;
    cudaGetSymbolAddress((void**)&s0, g_s0);
    cudaGetSymbolAddress((void**)&s1, g_s1);

    softmax_kernel<<<1, 32>>>(alphas);
    prep_w_kernel<<<(8 * C * 18 * C) / 256, 256>>>(w_conv3, w_dil3);

    const int smem1x1 = (C * WS_STRIDE + C * 64) * sizeof(float);
    cudaFuncSetAttribute(conv1x1_kernel, cudaFuncAttributeMaxDynamicSharedMemorySize, smem1x1);
    conv1x1_kernel<<<1024, 256, smem1x1>>>(input0, w_pre0, s0);
    conv1x1_kernel<<<1024, 256, smem1x1>>>(input1, w_pre1, s1);

    dim3 ngrid(16, 64);
    node_kernel<<<ngrid, 256>>>(s0, C * HW, s1, C * HW, 0, 1, out + 0 * C * HW);
    node_kernel<<<ngrid, 256>>>(s1, C * HW, out + 0 * C * HW, OUTC * HW, 2, 3, out + 1 * C * HW);
    node_kernel<<<ngrid, 256>>>(out + 0 * C * HW, OUTC * HW, out + 1 * C * HW, OUTC * HW, 4, 5,
                                out + 2 * C * HW);
    node_kernel<<<ngrid, 256>>>(out + 1 * C * HW, OUTC * HW, out + 2 * C * HW, OUTC * HW, 6, 7,
                                out + 3 * C * HW);

    copy_skip_kernel<<<(B * C * HW / 4) / 256, 256>>>(skip, out);
}

// round 6
// speedup vs baseline: 1.7949x; 1.0938x over previous
#include <cuda_runtime.h>
#include <cstdint>

#define B 64
#define C 128
#define H 32
#define W 32
#define HW 1024
#define OUTC 640
#define WS_STRIDE 132

typedef unsigned long long u64;

// ---- packed fp32x2 helpers (Blackwell FFMA2 — ptxas never emits this from C++) ----
__device__ __forceinline__ u64 pk2(float lo, float hi) {
    u64 r;
    asm("mov.b64 %0, {%1, %2};" : "=l"(r) : "f"(lo), "f"(hi));
    return r;
}
__device__ __forceinline__ void ffma2(u64& d, u64 a, u64 b) {
    asm("fma.rn.f32x2 %0, %1, %2, %0;" : "+l"(d) : "l"(a), "l"(b));
}
__device__ __forceinline__ void fadd2(u64& d, u64 a) {
    asm("add.rn.f32x2 %0, %0, %1;" : "+l"(d) : "l"(a));
}
__device__ __forceinline__ float2 upk(u64 v) {
    float2 r;
    asm("mov.b64 {%0, %1}, %2;" : "=f"(r.x), "=f"(r.y) : "l"(v));
    return r;
}

// ---- cp.async helpers ----
__device__ __forceinline__ void cp4(uint32_t s, const void* g, int sz) {
    asm volatile("cp.async.ca.shared.global [%0], [%1], 4, %2;" :: "r"(s), "l"(g), "r"(sz));
}
__device__ __forceinline__ void cp16(uint32_t s, const void* g) {
    asm volatile("cp.async.cg.shared.global [%0], [%1], 16;" :: "r"(s), "l"(g));
}
__device__ __forceinline__ void cp_commit() {
    asm volatile("cp.async.commit_group;");
}
__device__ __forceinline__ void cp_wait_all() {
    asm volatile("cp.async.wait_group 0;");
}

// ---------------- device scratch ---------------
__device__ float g_s0[B * C * HW];
__device__ float g_s1[B * C * HW];
__device__ float g_alpha[8][5];
__device__ float g_wcomb[8 * C * 18 * C];   // [edge][ic][tap(0..8 conv,9..17 dil)][oc], alpha-scaled

// ---------------- softmax over alpha rows ----------------
__global__ void softmax_kernel(const float* __restrict__ alphas) {
    int r = threadIdx.x;
    if (r < 8) {
        float m = -3.4e38f;
        #pragma unroll
        for (int j = 0; j < 5; j++) m = fmaxf(m, alphas[r * 5 + j]);
        float e[5], s = 0.f;
        #pragma unroll
        for (int j = 0; j < 5; j++) { e[j] = expf(alphas[r * 5 + j] - m); s += e[j]; }
        float inv = 1.f / s;
        #pragma unroll
        for (int j = 0; j < 5; j++) g_alpha[r][j] = e[j] * inv;
    }
}

// ---------------- weight transpose + alpha pre-scale ----------------
__global__ void prep_w_kernel(const float* __restrict__ wc, const float* __restrict__ wd) {
    int idx = blockIdx.x * blockDim.x + threadIdx.x;
    if (idx >= 8 * C * 18 * C) return;
    int oc = idx & 127;
    int rest = idx >> 7;
    int tap = rest % 18;
    int rest2 = rest / 18;
    int ic = rest2 & 127;
    int e = rest2 >> 7;
    float v;
    if (tap < 9) v = g_alpha[e][1] * wc[((e * C + oc) * C + ic) * 9 + tap];
    else         v = g_alpha[e][2] * wd[((e * C + oc) * C + ic) * 9 + (tap - 9)];
    g_wcomb[idx] = v;
}

// ---------------- 1x1 conv (preprocess) with packed FFMA2 ----------------
__global__ __launch_bounds__(256) void conv1x1_kernel(const float* __restrict__ in,
                                                      const float* __restrict__ w,
                                                      float* __restrict__ out) {
    extern __shared__ float sm[];
    float* ws = sm;
    float* ins = sm + C * WS_STRIDE;
    int t = threadIdx.x;
    int n = blockIdx.x >> 4;
    int hw0 = (blockIdx.x & 15) << 6;

    for (int i = t; i < C * C; i += 256) {
        int oc = i >> 7, ic = i & 127;
        ws[ic * WS_STRIDE + oc] = w[i];
    }
    const float4* inb = (const float4*)(in + (long)n * C * HW + hw0);
    float4* insv = (float4*)ins;
    for (int i = t; i < C * 16; i += 256) {
        int ic = i >> 4, p4 = i & 15;
        insv[ic * 16 + p4] = inb[ic * (HW / 4) + p4];
    }
    __syncthreads();

    int pg = t & 15, og = t >> 4;
    int ocb = og * 8;
    u64 acc2[4][4];
    #pragma unroll
    for (int k = 0; k < 4; k++)
        #pragma unroll
        for (int j = 0; j < 4; j++) acc2[k][j] = 0ull;

    for (int ic = 0; ic < C; ic++) {
        float4 iv = *(const float4*)&ins[ic * 64 + pg * 4];
        float4 wa = *(const float4*)&ws[ic * WS_STRIDE + ocb];
        float4 wb = *(const float4*)&ws[ic * WS_STRIDE + ocb + 4];
        u64 w0 = pk2(wa.x, wa.y), w1 = pk2(wa.z, wa.w);
        u64 w2 = pk2(wb.x, wb.y), w3 = pk2(wb.z, wb.w);
        float xv[4] = {iv.x, iv.y, iv.z, iv.w};
        #pragma unroll
        for (int k = 0; k < 4; k++) {
            u64 xd = pk2(xv[k], xv[k]);
            ffma2(acc2[k][0], xd, w0);
            ffma2(acc2[k][1], xd, w1);
            ffma2(acc2[k][2], xd, w2);
            ffma2(acc2[k][3], xd, w3);
        }
    }

    float* ob = out + (long)n * C * HW + hw0 + pg * 4;
    #pragma unroll
    for (int jp = 0; jp < 4; jp++) {
        float2 v0 = upk(acc2[0][jp]), v1 = upk(acc2[1][jp]);
        float2 v2 = upk(acc2[2][jp]), v3 = upk(acc2[3][jp]);
        *(float4*)&ob[(ocb + 2 * jp) * HW]     = make_float4(v0.x, v1.x, v2.x, v3.x);
        *(float4*)&ob[(ocb + 2 * jp + 1) * HW] = make_float4(v0.y, v1.y, v2.y, v3.y);
    }
}

// ---------------- fused node kernel v2: 8x16 px tile, 8px x 8oc per thread,
//                  cp.async double-buffered weight+input staging ----------------
__global__ __launch_bounds__(256) void node_kernel(const float* __restrict__ h0, int h0_bs,
                                                   const float* __restrict__ h1, int h1_bs,
                                                   int e0, int e1,
                                                   float* __restrict__ out) {
    __shared__ float in_s[2][12][24];     // rows -2..9, cols -2..17 (cols 20..23 pad)
    __shared__ float ws_s[2][2304];       // [tap 0..17][oc 0..127]

    int t = threadIdx.x;
    int og = t >> 4;                 // 0..15 -> oc group of 8
    int pg = t & 15;
    int r  = pg >> 1;                // tile row 0..7
    int cb = (pg & 1) * 8;           // tile col base 0 or 8
    int ocb = og * 8;
    int b = blockIdx.y;
    int tile = blockIdx.x;           // 0..7
    int y0 = (tile >> 1) * 8;        // 0,8,16,24
    int x0 = (tile & 1) * 16;        // 0,16

    u64 acc2[8][4];
    #pragma unroll
    for (int k = 0; k < 8; k++)
        #pragma unroll
        for (int j = 0; j < 4; j++) acc2[k][j] = 0ull;

    float a0A = g_alpha[e0][0], a3A = g_alpha[e0][3] * (1.f / 9.f), a4A = g_alpha[e0][4];
    float a0B = g_alpha[e1][0], a3B = g_alpha[e1][3] * (1.f / 9.f), a4B = g_alpha[e1][4];

    const float* hb0 = h0 + (long)b * h0_bs;
    const float* hb1 = h1 + (long)b * h1_bs;

    uint32_t in_base = (uint32_t)__cvta_generic_to_shared(&in_s[0][0][0]);
    uint32_t ws_base = (uint32_t)__cvta_generic_to_shared(&ws_s[0][0]);

    // this thread's fixed input-staging slot (threads 0..239)
    int srow = t / 20, scol = t - srow * 20;
    int gy_s = y0 + srow - 2, gx_s = x0 + scol - 2;
    bool sok = ((unsigned)gy_s < 32u) && ((unsigned)gx_s < 32u) && (t < 240);
    int soff = sok ? (gy_s * 32 + gx_s) : 0;
    int ssz = sok ? 4 : 0;
    uint32_t in_dst0 = in_base + (uint32_t)(srow * 24 + scol) * 4;

#define STAGE(icn) do {                                                        \
    int ch_ = (icn) & 127;                                                     \
    const float* hb_ = ((icn) < C) ? hb0 : hb1;                                \
    int e_ = ((icn) < C) ? e0 : e1;                                            \
    int bf_ = (icn) & 1;                                                       \
    if (t < 240) cp4(in_dst0 + bf_ * (288 * 4), hb_ + ch_ * HW + soff, ssz);   \
    const float* wsrc_ = g_wcomb + ((size_t)(e_ * C + ch_)) * 2304;            \
    _Pragma("unroll")                                                          \
    for (int i_ = t; i_ < 576; i_ += 256)                                      \
        cp16(ws_base + (uint32_t)(bf_ * 2304 + i_ * 4) * 4, wsrc_ + i_ * 4);   \
    cp_commit();                                                               \
} while (0)

    STAGE(0);

    for (int ic = 0; ic < 2 * C; ic++) {
        cp_wait_all();
        __syncthreads();
        if (ic + 1 < 2 * C) STAGE(ic + 1);

        int bf = ic & 1;

        // stage 5 rows x 12 cols into registers (rows r..r+4 = tile rows r-2..r+2)
        float iv[5][12];
        #pragma unroll
        for (int dy = 0; dy < 5; dy++) {
            float4 v0 = *(const float4*)&in_s[bf][r + dy][cb];
            float4 v1 = *(const float4*)&in_s[bf][r + dy][cb + 4];
            float4 v2 = *(const float4*)&in_s[bf][r + dy][cb + 8];
            iv[dy][0] = v0.x; iv[dy][1] = v0.y; iv[dy][2]  = v0.z; iv[dy][3]  = v0.w;
            iv[dy][4] = v1.x; iv[dy][5] = v1.y; iv[dy][6]  = v1.z; iv[dy][7]  = v1.w;
            iv[dy][8] = v2.x; iv[dy][9] = v2.y; iv[dy][10] = v2.z; iv[dy][11] = v2.w;
        }

        const float* wsp = &ws_s[bf][0];
        #pragma unroll
        for (int ty = 0; ty < 3; ty++) {
            #pragma unroll
            for (int tx = 0; tx < 3; tx++) {
                int tap = ty * 3 + tx;
                {   // regular conv taps
                    float4 wa = *(const float4*)&wsp[tap * 128 + ocb];
                    float4 wb = *(const float4*)&wsp[tap * 128 + ocb + 4];
                    u64 w0 = pk2(wa.x, wa.y), w1 = pk2(wa.z, wa.w);
                    u64 w2 = pk2(wb.x, wb.y), w3 = pk2(wb.z, wb.w);
                    #pragma unroll
                    for (int k = 0; k < 8; k++) {
                        float x = iv[ty + 1][tx + 1 + k];
                        u64 xd = pk2(x, x);
                        ffma2(acc2[k][0], xd, w0);
                        ffma2(acc2[k][1], xd, w1);
                        ffma2(acc2[k][2], xd, w2);
                        ffma2(acc2[k][3], xd, w3);
                    }
                }
                {   // dilated conv taps
                    float4 da = *(const float4*)&wsp[(9 + tap) * 128 + ocb];
                    float4 db = *(const float4*)&wsp[(9 + tap) * 128 + ocb + 4];
                    u64 d0 = pk2(da.x, da.y), d1 = pk2(da.z, da.w);
                    u64 d2 = pk2(db.x, db.y), d3 = pk2(db.z, db.w);
                    #pragma unroll
                    for (int k = 0; k < 8; k++) {
                        float x = iv[2 * ty][2 * tx + k];
                        u64 xd = pk2(x, x);
                        ffma2(acc2[k][0], xd, d0);
                        ffma2(acc2[k][1], xd, d1);
                        ffma2(acc2[k][2], xd, d2);
                        ffma2(acc2[k][3], xd, d3);
                    }
                }
            }
        }

        // identity + avg pool + max pool: thread group owning oc == ch adds pooled terms
        int ch = ic & 127;
        if ((ch >> 3) == og) {
            float a0, a3, a4;
            if (ic < C) { a0 = a0A; a3 = a3A; a4 = a4A; }
            else        { a0 = a0B; a3 = a3B; a4 = a4B; }
            int l = ch & 7;
            #pragma unroll
            for (int k = 0; k < 8; k++) {
                float s9 = 0.f, m = -3.4e38f;
                #pragma unroll
                for (int dy = -1; dy <= 1; dy++) {
                    #pragma unroll
                    for (int dx = -1; dx <= 1; dx++) {
                        float val = iv[2 + dy][2 + k + dx];
                        s9 += val;   // zero-padded tile -> count_include_pad avg correct
                        int gy = y0 + r + dy, gx = x0 + cb + k + dx;
                        if ((unsigned)gy < 32u && (unsigned)gx < 32u) m = fmaxf(m, val);
                    }
                }
                float p = a0 * iv[2][2 + k] + a3 * s9 + a4 * m;
                u64 pp = (l & 1) ? pk2(0.f, p) : pk2(p, 0.f);
                fadd2(acc2[k][l >> 1], pp);
            }
        }
    }
#undef STAGE

    float* ob = out + (long)b * (OUTC * HW) + (y0 + r) * W + x0 + cb;
    #pragma unroll
    for (int jp = 0; jp < 4; jp++) {
        float2 v0 = upk(acc2[0][jp]), v1 = upk(acc2[1][jp]);
        float2 v2 = upk(acc2[2][jp]), v3 = upk(acc2[3][jp]);
        float2 v4 = upk(acc2[4][jp]), v5 = upk(acc2[5][jp]);
        float2 v6 = upk(acc2[6][jp]), v7 = upk(acc2[7][jp]);
        float* plo = &ob[(ocb + 2 * jp) * HW];
        float* phi = &ob[(ocb + 2 * jp + 1) * HW];
        *(float4*)plo       = make_float4(v0.x, v1.x, v2.x, v3.x);
        *(float4*)(plo + 4) = make_float4(v4.x, v5.x, v6.x, v7.x);
        *(float4*)phi       = make_float4(v0.y, v1.y, v2.y, v3.y);
        *(float4*)(phi + 4) = make_float4(v4.y, v5.y, v6.y, v7.y);
    }
}

// ---------------- skip copies ----------------
__global__ void copy_skip_kernel(const float* __restrict__ skip, float* __restrict__ out) {
    int idx = blockIdx.x * blockDim.x + threadIdx.x;
    float4 v = ((const float4*)skip)[idx];
    int hw4 = idx & 255;
    int c = (idx >> 8) & 127;
    int n = idx >> 15;
    ((float4*)out)[(long)n * (OUTC * HW / 4) + (512 + c) * (HW / 4) + hw4] = v;
    ((float4*)out)[(long)B * OUTC * HW / 4 + idx] = v;
}

// ---------------- launch ----------------
extern "C" void kernel_launch(void* const* d_in, const int* in_sizes, int n_in,
                              void* d_out, int out_size) {
    const float* input0  = (const float*)d_in[0];
    const float* input1  = (const float*)d_in[1];
    const float* skip    = (const float*)d_in[2];
    const float* w_pre0  = (const float*)d_in[3];
    const float* w_pre1  = (const float*)d_in[4];
    const float* w_conv3 = (const float*)d_in[5];
    const float* w_dil3  = (const float*)d_in[6];
    const float* alphas  = (const float*)d_in[7];
    float* out = (float*)d_out;

    float *s0, *s1;
    cudaGetSymbolAddress((void**)&s0, g_s0);
    cudaGetSymbolAddress((void**)&s1, g_s1);

    softmax_kernel<<<1, 32>>>(alphas);
    prep_w_kernel<<<(8 * C * 18 * C) / 256, 256>>>(w_conv3, w_dil3);

    const int smem1x1 = (C * WS_STRIDE + C * 64) * sizeof(float);
    cudaFuncSetAttribute(conv1x1_kernel, cudaFuncAttributeMaxDynamicSharedMemorySize, smem1x1);
    conv1x1_kernel<<<1024, 256, smem1x1>>>(input0, w_pre0, s0);
    conv1x1_kernel<<<1024, 256, smem1x1>>>(input1, w_pre1, s1);

    dim3 ngrid(8, 64);
    node_kernel<<<ngrid, 256>>>(s0, C * HW, s1, C * HW, 0, 1, out + 0 * C * HW);
    node_kernel<<<ngrid, 256>>>(s1, C * HW, out + 0 * C * HW, OUTC * HW, 2, 3, out + 1 * C * HW);
    node_kernel<<<ngrid, 256>>>(out + 0 * C * HW, OUTC * HW, out + 1 * C * HW, OUTC * HW, 4, 5,
                                out + 2 * C * HW);
    node_kernel<<<ngrid, 256>>>(out + 1 * C * HW, OUTC * HW, out + 2 * C * HW, OUTC * HW, 6, 7,
                                out + 3 * C * HW);

    copy_skip_kernel<<<(B * C * HW / 4) / 256, 256>>>(skip, out);
}

// round 7
// speedup vs baseline: 1.7967x; 1.0010x over previous
#include <cuda_runtime.h>
#include <cstdint>

#define B 64
#define C 128
#define H 32
#define W 32
#define HW 1024
#define OUTC 640
#define WS_STRIDE 132

typedef unsigned long long u64;

// ---- packed fp32x2 helpers (Blackwell FFMA2 — ptxas never emits this from C++) ----
__device__ __forceinline__ u64 pk2(float lo, float hi) {
    u64 r;
    asm("mov.b64 %0, {%1, %2};" : "=l"(r) : "f"(lo), "f"(hi));
    return r;
}
__device__ __forceinline__ void ffma2(u64& d, u64 a, u64 b) {
    asm("fma.rn.f32x2 %0, %1, %2, %0;" : "+l"(d) : "l"(a), "l"(b));
}
__device__ __forceinline__ void fadd2(u64& d, u64 a) {
    asm("add.rn.f32x2 %0, %0, %1;" : "+l"(d) : "l"(a));
}
__device__ __forceinline__ float2 upk(u64 v) {
    float2 r;
    asm("mov.b64 {%0, %1}, %2;" : "=f"(r.x), "=f"(r.y) : "l"(v));
    return r;
}

// ---- cp.async helpers ----
__device__ __forceinline__ void cp4(uint32_t s, const void* g, int sz) {
    asm volatile("cp.async.ca.shared.global [%0], [%1], 4, %2;" :: "r"(s), "l"(g), "r"(sz));
}
__device__ __forceinline__ void cp16(uint32_t s, const void* g) {
    asm volatile("cp.async.cg.shared.global [%0], [%1], 16;" :: "r"(s), "l"(g));
}
__device__ __forceinline__ void cp_commit() {
    asm volatile("cp.async.commit_group;");
}
__device__ __forceinline__ void cp_wait_all() {
    asm volatile("cp.async.wait_group 0;");
}

// ---------------- device scratch ---------------
__device__ float g_s0[B * C * HW];
__device__ float g_s1[B * C * HW];
__device__ float g_alpha[8][5];
__device__ float g_wcomb[8 * C * 18 * C];   // [edge][ic][tap(0..8 conv,9..17 dil)][oc], alpha-scaled

// ---------------- softmax over alpha rows ----------------
__global__ void softmax_kernel(const float* __restrict__ alphas) {
    int r = threadIdx.x;
    if (r < 8) {
        float m = -3.4e38f;
        #pragma unroll
        for (int j = 0; j < 5; j++) m = fmaxf(m, alphas[r * 5 + j]);
        float e[5], s = 0.f;
        #pragma unroll
        for (int j = 0; j < 5; j++) { e[j] = expf(alphas[r * 5 + j] - m); s += e[j]; }
        float inv = 1.f / s;
        #pragma unroll
        for (int j = 0; j < 5; j++) g_alpha[r][j] = e[j] * inv;
    }
}

// ---------------- weight transpose + alpha pre-scale ----------------
__global__ void prep_w_kernel(const float* __restrict__ wc, const float* __restrict__ wd) {
    int idx = blockIdx.x * blockDim.x + threadIdx.x;
    if (idx >= 8 * C * 18 * C) return;
    int oc = idx & 127;
    int rest = idx >> 7;
    int tap = rest % 18;
    int rest2 = rest / 18;
    int ic = rest2 & 127;
    int e = rest2 >> 7;
    float v;
    if (tap < 9) v = g_alpha[e][1] * wc[((e * C + oc) * C + ic) * 9 + tap];
    else         v = g_alpha[e][2] * wd[((e * C + oc) * C + ic) * 9 + (tap - 9)];
    g_wcomb[idx] = v;
}

// ---------------- 1x1 conv (preprocess) with packed FFMA2 ----------------
__global__ __launch_bounds__(256) void conv1x1_kernel(const float* __restrict__ in,
                                                      const float* __restrict__ w,
                                                      float* __restrict__ out) {
    extern __shared__ float sm[];
    float* ws = sm;
    float* ins = sm + C * WS_STRIDE;
    int t = threadIdx.x;
    int n = blockIdx.x >> 4;
    int hw0 = (blockIdx.x & 15) << 6;

    for (int i = t; i < C * C; i += 256) {
        int oc = i >> 7, ic = i & 127;
        ws[ic * WS_STRIDE + oc] = w[i];
    }
    const float4* inb = (const float4*)(in + (long)n * C * HW + hw0);
    float4* insv = (float4*)ins;
    for (int i = t; i < C * 16; i += 256) {
        int ic = i >> 4, p4 = i & 15;
        insv[ic * 16 + p4] = inb[ic * (HW / 4) + p4];
    }
    __syncthreads();

    int pg = t & 15, og = t >> 4;
    int ocb = og * 8;
    u64 acc2[4][4];
    #pragma unroll
    for (int k = 0; k < 4; k++)
        #pragma unroll
        for (int j = 0; j < 4; j++) acc2[k][j] = 0ull;

    for (int ic = 0; ic < C; ic++) {
        float4 iv = *(const float4*)&ins[ic * 64 + pg * 4];
        float4 wa = *(const float4*)&ws[ic * WS_STRIDE + ocb];
        float4 wb = *(const float4*)&ws[ic * WS_STRIDE + ocb + 4];
        u64 w0 = pk2(wa.x, wa.y), w1 = pk2(wa.z, wa.w);
        u64 w2 = pk2(wb.x, wb.y), w3 = pk2(wb.z, wb.w);
        float xv[4] = {iv.x, iv.y, iv.z, iv.w};
        #pragma unroll
        for (int k = 0; k < 4; k++) {
            u64 xd = pk2(xv[k], xv[k]);
            ffma2(acc2[k][0], xd, w0);
            ffma2(acc2[k][1], xd, w1);
            ffma2(acc2[k][2], xd, w2);
            ffma2(acc2[k][3], xd, w3);
        }
    }

    float* ob = out + (long)n * C * HW + hw0 + pg * 4;
    #pragma unroll
    for (int jp = 0; jp < 4; jp++) {
        float2 v0 = upk(acc2[0][jp]), v1 = upk(acc2[1][jp]);
        float2 v2 = upk(acc2[2][jp]), v3 = upk(acc2[3][jp]);
        *(float4*)&ob[(ocb + 2 * jp) * HW]     = make_float4(v0.x, v1.x, v2.x, v3.x);
        *(float4*)&ob[(ocb + 2 * jp + 1) * HW] = make_float4(v0.y, v1.y, v2.y, v3.y);
    }
}

// ---------------- fused node kernel v2: 8x16 px tile, 8px x 8oc per thread,
//                  cp.async double-buffered weight+input staging ----------------
__global__ __launch_bounds__(256) void node_kernel(const float* __restrict__ h0, int h0_bs,
                                                   const float* __restrict__ h1, int h1_bs,
                                                   int e0, int e1,
                                                   float* __restrict__ out) {
    __shared__ float in_s[2][12][24];     // rows -2..9, cols -2..17 (cols 20..23 pad)
    __shared__ float ws_s[2][2304];       // [tap 0..17][oc 0..127]

    int t = threadIdx.x;
    int og = t >> 4;                 // 0..15 -> oc group of 8
    int pg = t & 15;
    int r  = pg >> 1;                // tile row 0..7
    int cb = (pg & 1) * 8;           // tile col base 0 or 8
    int ocb = og * 8;
    int b = blockIdx.y;
    int tile = blockIdx.x;           // 0..7
    int y0 = (tile >> 1) * 8;        // 0,8,16,24
    int x0 = (tile & 1) * 16;        // 0,16

    u64 acc2[8][4];
    #pragma unroll
    for (int k = 0; k < 8; k++)
        #pragma unroll
        for (int j = 0; j < 4; j++) acc2[k][j] = 0ull;

    float a0A = g_alpha[e0][0], a3A = g_alpha[e0][3] * (1.f / 9.f), a4A = g_alpha[e0][4];
    float a0B = g_alpha[e1][0], a3B = g_alpha[e1][3] * (1.f / 9.f), a4B = g_alpha[e1][4];

    const float* hb0 = h0 + (long)b * h0_bs;
    const float* hb1 = h1 + (long)b * h1_bs;

    uint32_t in_base = (uint32_t)__cvta_generic_to_shared(&in_s[0][0][0]);
    uint32_t ws_base = (uint32_t)__cvta_generic_to_shared(&ws_s[0][0]);

    // this thread's fixed input-staging slot (threads 0..239)
    int srow = t / 20, scol = t - srow * 20;
    int gy_s = y0 + srow - 2, gx_s = x0 + scol - 2;
    bool sok = ((unsigned)gy_s < 32u) && ((unsigned)gx_s < 32u) && (t < 240);
    int soff = sok ? (gy_s * 32 + gx_s) : 0;
    int ssz = sok ? 4 : 0;
    uint32_t in_dst0 = in_base + (uint32_t)(srow * 24 + scol) * 4;

#define STAGE(icn) do {                                                        \
    int ch_ = (icn) & 127;                                                     \
    const float* hb_ = ((icn) < C) ? hb0 : hb1;                                \
    int e_ = ((icn) < C) ? e0 : e1;                                            \
    int bf_ = (icn) & 1;                                                       \
    if (t < 240) cp4(in_dst0 + bf_ * (288 * 4), hb_ + ch_ * HW + soff, ssz);   \
    const float* wsrc_ = g_wcomb + ((size_t)(e_ * C + ch_)) * 2304;            \
    _Pragma("unroll")                                                          \
    for (int i_ = t; i_ < 576; i_ += 256)                                      \
        cp16(ws_base + (uint32_t)(bf_ * 2304 + i_ * 4) * 4, wsrc_ + i_ * 4);   \
    cp_commit();                                                               \
} while (0)

    STAGE(0);

    for (int ic = 0; ic < 2 * C; ic++) {
        cp_wait_all();
        __syncthreads();
        if (ic + 1 < 2 * C) STAGE(ic + 1);

        int bf = ic & 1;

        // stage 5 rows x 12 cols into registers (rows r..r+4 = tile rows r-2..r+2)
        float iv[5][12];
        #pragma unroll
        for (int dy = 0; dy < 5; dy++) {
            float4 v0 = *(const float4*)&in_s[bf][r + dy][cb];
            float4 v1 = *(const float4*)&in_s[bf][r + dy][cb + 4];
            float4 v2 = *(const float4*)&in_s[bf][r + dy][cb + 8];
            iv[dy][0] = v0.x; iv[dy][1] = v0.y; iv[dy][2]  = v0.z; iv[dy][3]  = v0.w;
            iv[dy][4] = v1.x; iv[dy][5] = v1.y; iv[dy][6]  = v1.z; iv[dy][7]  = v1.w;
            iv[dy][8] = v2.x; iv[dy][9] = v2.y; iv[dy][10] = v2.z; iv[dy][11] = v2.w;
        }

        const float* wsp = &ws_s[bf][0];
        #pragma unroll
        for (int ty = 0; ty < 3; ty++) {
            #pragma unroll
            for (int tx = 0; tx < 3; tx++) {
                int tap = ty * 3 + tx;
                {   // regular conv taps
                    float4 wa = *(const float4*)&wsp[tap * 128 + ocb];
                    float4 wb = *(const float4*)&wsp[tap * 128 + ocb + 4];
                    u64 w0 = pk2(wa.x, wa.y), w1 = pk2(wa.z, wa.w);
                    u64 w2 = pk2(wb.x, wb.y), w3 = pk2(wb.z, wb.w);
                    #pragma unroll
                    for (int k = 0; k < 8; k++) {
                        float x = iv[ty + 1][tx + 1 + k];
                        u64 xd = pk2(x, x);
                        ffma2(acc2[k][0], xd, w0);
                        ffma2(acc2[k][1], xd, w1);
                        ffma2(acc2[k][2], xd, w2);
                        ffma2(acc2[k][3], xd, w3);
                    }
                }
                {   // dilated conv taps
                    float4 da = *(const float4*)&wsp[(9 + tap) * 128 + ocb];
                    float4 db = *(const float4*)&wsp[(9 + tap) * 128 + ocb + 4];
                    u64 d0 = pk2(da.x, da.y), d1 = pk2(da.z, da.w);
                    u64 d2 = pk2(db.x, db.y), d3 = pk2(db.z, db.w);
                    #pragma unroll
                    for (int k = 0; k < 8; k++) {
                        float x = iv[2 * ty][2 * tx + k];
                        u64 xd = pk2(x, x);
                        ffma2(acc2[k][0], xd, d0);
                        ffma2(acc2[k][1], xd, d1);
                        ffma2(acc2[k][2], xd, d2);
                        ffma2(acc2[k][3], xd, d3);
                    }
                }
            }
        }

        // identity + avg pool + max pool: thread group owning oc == ch adds pooled terms
        int ch = ic & 127;
        if ((ch >> 3) == og) {
            float a0, a3, a4;
            if (ic < C) { a0 = a0A; a3 = a3A; a4 = a4A; }
            else        { a0 = a0B; a3 = a3B; a4 = a4B; }
            int l = ch & 7;
            #pragma unroll
            for (int k = 0; k < 8; k++) {
                float s9 = 0.f, m = -3.4e38f;
                #pragma unroll
                for (int dy = -1; dy <= 1; dy++) {
                    #pragma unroll
                    for (int dx = -1; dx <= 1; dx++) {
                        float val = iv[2 + dy][2 + k + dx];
                        s9 += val;   // zero-padded tile -> count_include_pad avg correct
                        int gy = y0 + r + dy, gx = x0 + cb + k + dx;
                        if ((unsigned)gy < 32u && (unsigned)gx < 32u) m = fmaxf(m, val);
                    }
                }
                float p = a0 * iv[2][2 + k] + a3 * s9 + a4 * m;
                u64 pp = (l & 1) ? pk2(0.f, p) : pk2(p, 0.f);
                fadd2(acc2[k][l >> 1], pp);
            }
        }
    }
#undef STAGE

    float* ob = out + (long)b * (OUTC * HW) + (y0 + r) * W + x0 + cb;
    #pragma unroll
    for (int jp = 0; jp < 4; jp++) {
        float2 v0 = upk(acc2[0][jp]), v1 = upk(acc2[1][jp]);
        float2 v2 = upk(acc2[2][jp]), v3 = upk(acc2[3][jp]);
        float2 v4 = upk(acc2[4][jp]), v5 = upk(acc2[5][jp]);
        float2 v6 = upk(acc2[6][jp]), v7 = upk(acc2[7][jp]);
        float* plo = &ob[(ocb + 2 * jp) * HW];
        float* phi = &ob[(ocb + 2 * jp + 1) * HW];
        *(float4*)plo       = make_float4(v0.x, v1.x, v2.x, v3.x);
        *(float4*)(plo + 4) = make_float4(v4.x, v5.x, v6.x, v7.x);
        *(float4*)phi       = make_float4(v0.y, v1.y, v2.y, v3.y);
        *(float4*)(phi + 4) = make_float4(v4.y, v5.y, v6.y, v7.y);
    }
}

// ---------------- skip copies ----------------
__global__ void copy_skip_kernel(const float* __restrict__ skip, float* __restrict__ out) {
    int idx = blockIdx.x * blockDim.x + threadIdx.x;
    float4 v = ((const float4*)skip)[idx];
    int hw4 = idx & 255;
    int c = (idx >> 8) & 127;
    int n = idx >> 15;
    ((float4*)out)[(long)n * (OUTC * HW / 4) + (512 + c) * (HW / 4) + hw4] = v;
    ((float4*)out)[(long)B * OUTC * HW / 4 + idx] = v;
}

// ---------------- launch ----------------
extern "C" void kernel_launch(void* const* d_in, const int* in_sizes, int n_in,
                              void* d_out, int out_size) {
    const float* input0  = (const float*)d_in[0];
    const float* input1  = (const float*)d_in[1];
    const float* skip    = (const float*)d_in[2];
    const float* w_pre0  = (const float*)d_in[3];
    const float* w_pre1  = (const float*)d_in[4];
    const float* w_conv3 = (const float*)d_in[5];
    const float* w_dil3  = (const float*)d_in[6];
    const float* alphas  = (const float*)d_in[7];
    float* out = (float*)d_out;

    float *s0, *s1;
    cudaGetSymbolAddress((void**)&s0, g_s0);
    cudaGetSymbolAddress((void**)&s1, g_s1);

    softmax_kernel<<<1, 32>>>(alphas);
    prep_w_kernel<<<(8 * C * 18 * C) / 256, 256>>>(w_conv3, w_dil3);

    const int smem1x1 = (C * WS_STRIDE + C * 64) * sizeof(float);
    cudaFuncSetAttribute(conv1x1_kernel, cudaFuncAttributeMaxDynamicSharedMemorySize, smem1x1);
    conv1x1_kernel<<<1024, 256, smem1x1>>>(input0, w_pre0, s0);
    conv1x1_kernel<<<1024, 256, smem1x1>>>(input1, w_pre1, s1);

    dim3 ngrid(8, 64);
    node_kernel<<<ngrid, 256>>>(s0, C * HW, s1, C * HW, 0, 1, out + 0 * C * HW);
    node_kernel<<<ngrid, 256>>>(s1, C * HW, out + 0 * C * HW, OUTC * HW, 2, 3, out + 1 * C * HW);
    node_kernel<<<ngrid, 256>>>(out + 0 * C * HW, OUTC * HW, out + 1 * C * HW, OUTC * HW, 4, 5,
                                out + 2 * C * HW);
    node_kernel<<<ngrid, 256>>>(out + 1 * C * HW, OUTC * HW, out + 2 * C * HW, OUTC * HW, 6, 7,
                                out + 3 * C * HW);

    copy_skip_kernel<<<(B * C * HW / 4) / 256, 256>>>(skip, out);
}

// round 11
// speedup vs baseline: 4.9238x; 2.7404x over previous
#include <cuda_runtime.h>
#include <cuda_bf16.h>
#include <cstdint>

#define B 64
#define C 128
#define HW 1024
#define OUTC 640
#define WS_STRIDE 132
#define WSZ (8*18*128*128)
#define ISZ (5L*64*36*36*128)

typedef unsigned long long u64;

__device__ __forceinline__ u64 pk2(float lo, float hi) {
    u64 r; asm("mov.b64 %0, {%1, %2};" : "=l"(r) : "f"(lo), "f"(hi)); return r;
}
__device__ __forceinline__ void ffma2(u64& d, u64 a, u64 b) {
    asm("fma.rn.f32x2 %0, %1, %2, %0;" : "+l"(d) : "l"(a), "l"(b));
}
__device__ __forceinline__ float2 upk(u64 v) {
    float2 r; asm("mov.b64 {%0, %1}, %2;" : "=f"(r.x), "=f"(r.y) : "l"(v)); return r;
}
__device__ __forceinline__ uint32_t s2u(const void* p) {
    return (uint32_t)__cvta_generic_to_shared(p);
}
__device__ __forceinline__ void cp16(uint32_t s, const void* g) {
    asm volatile("cp.async.cg.shared.global [%0], [%1], 16;" :: "r"(s), "l"(g));
}
__device__ __forceinline__ void cp_commit() { asm volatile("cp.async.commit_group;"); }

__device__ __forceinline__ void ldx4(uint32_t* r, uint32_t a) {
    asm volatile("ldmatrix.sync.aligned.m8n8.x4.shared.b16 {%0,%1,%2,%3}, [%4];"
        : "=r"(r[0]), "=r"(r[1]), "=r"(r[2]), "=r"(r[3]) : "r"(a));
}
__device__ __forceinline__ void mma16816(float* d, const uint32_t* a, uint32_t b0, uint32_t b1) {
    asm volatile("mma.sync.aligned.m16n8k16.row.col.f32.bf16.bf16.f32 "
        "{%0,%1,%2,%3}, {%4,%5,%6,%7}, {%8,%9}, {%0,%1,%2,%3};"
        : "+f"(d[0]), "+f"(d[1]), "+f"(d[2]), "+f"(d[3])
        : "r"(a[0]), "r"(a[1]), "r"(a[2]), "r"(a[3]), "r"(b0), "r"(b1));
}

// ---------------- device scratch ----------------
__device__ float g_s0[B * C * HW];
__device__ float g_s1[B * C * HW];
__device__ float g_alpha[8][5];
__device__ __nv_bfloat16 g_wA[2 * WSZ];              // [part][e][tap][oc][ic], folded weights
__device__ __nv_bfloat16 g_in[2 * ISZ];              // [part][st][b][py36][px36][c], zero halo
__device__ float g_max[5L * 64 * 128 * 1024];        // raw max3x3 per state, NCHW

// ---------------- softmax ----------------
__global__ void softmax_kernel(const float* __restrict__ alphas) {
    int r = threadIdx.x;
    if (r < 8) {
        float m = -3.4e38f;
        #pragma unroll
        for (int j = 0; j < 5; j++) m = fmaxf(m, alphas[r * 5 + j]);
        float e[5], s = 0.f;
        #pragma unroll
        for (int j = 0; j < 5; j++) { e[j] = expf(alphas[r * 5 + j] - m); s += e[j]; }
        float inv = 1.f / s;
        #pragma unroll
        for (int j = 0; j < 5; j++) g_alpha[r][j] = e[j] * inv;
    }
}

// ---------------- weight prep: alpha-scale + identity/avg fold + bf16 hi/lo split ----------------
__global__ void prep_w_kernel(const float* __restrict__ wc, const float* __restrict__ wd) {
    int idx = blockIdx.x * blockDim.x + threadIdx.x;
    if (idx >= WSZ) return;
    int ic = idx & 127;
    int oc = (idx >> 7) & 127;
    int r = idx >> 14;               // 0..143
    int tap = r % 18, e = r / 18;
    float v;
    if (tap < 9) {
        v = g_alpha[e][1] * wc[((e * 128 + oc) * 128 + ic) * 9 + tap];
        if (oc == ic) {
            v += g_alpha[e][3] * (1.f / 9.f);
            if (tap == 4) v += g_alpha[e][0];
        }
    } else {
        v = g_alpha[e][2] * wd[((e * 128 + oc) * 128 + ic) * 9 + tap - 9];
    }
    __nv_bfloat16 hi = __float2bfloat16(v);
    g_wA[idx] = hi;
    g_wA[WSZ + idx] = __float2bfloat16(v - __bfloat162float(hi));
}

// ---------------- 1x1 conv (FFMA2, unchanged) ----------------
__global__ __launch_bounds__(256) void conv1x1_kernel(const float* __restrict__ in,
                                                      const float* __restrict__ w,
                                                      float* __restrict__ out) {
    extern __shared__ float sm[];
    float* ws = sm;
    float* ins = sm + C * WS_STRIDE;
    int t = threadIdx.x;
    int n = blockIdx.x >> 4;
    int hw0 = (blockIdx.x & 15) << 6;

    for (int i = t; i < C * C; i += 256) {
        int oc = i >> 7, ic = i & 127;
        ws[ic * WS_STRIDE + oc] = w[i];
    }
    const float4* inb = (const float4*)(in + (long)n * C * HW + hw0);
    float4* insv = (float4*)ins;
    for (int i = t; i < C * 16; i += 256) {
        int ic = i >> 4, p4 = i & 15;
        insv[ic * 16 + p4] = inb[ic * (HW / 4) + p4];
    }
    __syncthreads();

    int pg = t & 15, og = t >> 4;
    int ocb = og * 8;
    u64 acc2[4][4];
    #pragma unroll
    for (int k = 0; k < 4; k++)
        #pragma unroll
        for (int j = 0; j < 4; j++) acc2[k][j] = 0ull;

    for (int ic = 0; ic < C; ic++) {
        float4 iv = *(const float4*)&ins[ic * 64 + pg * 4];
        float4 wa = *(const float4*)&ws[ic * WS_STRIDE + ocb];
        float4 wb = *(const float4*)&ws[ic * WS_STRIDE + ocb + 4];
        u64 w0 = pk2(wa.x, wa.y), w1 = pk2(wa.z, wa.w);
        u64 w2 = pk2(wb.x, wb.y), w3 = pk2(wb.z, wb.w);
        float xv[4] = {iv.x, iv.y, iv.z, iv.w};
        #pragma unroll
        for (int k = 0; k < 4; k++) {
            u64 xd = pk2(xv[k], xv[k]);
            ffma2(acc2[k][0], xd, w0);
            ffma2(acc2[k][1], xd, w1);
            ffma2(acc2[k][2], xd, w2);
            ffma2(acc2[k][3], xd, w3);
        }
    }

    float* ob = out + (long)n * C * HW + hw0 + pg * 4;
    #pragma unroll
    for (int jp = 0; jp < 4; jp++) {
        float2 v0 = upk(acc2[0][jp]), v1 = upk(acc2[1][jp]);
        float2 v2 = upk(acc2[2][jp]), v3 = upk(acc2[3][jp]);
        *(float4*)&ob[(ocb + 2 * jp) * HW]     = make_float4(v0.x, v1.x, v2.x, v3.x);
        *(float4*)&ob[(ocb + 2 * jp + 1) * HW] = make_float4(v0.y, v1.y, v2.y, v3.y);
    }
}

// ---------------- postprep: fp32 NCHW state -> padded NHWC bf16 hi/lo + raw max3x3 ----------------
__global__ __launch_bounds__(256) void postprep_kernel(const float* __restrict__ src,
                                                       long bstride, int st) {
    __shared__ float rows[3][64 * 33];
    int y = blockIdx.x, ch = blockIdx.y, b = blockIdx.z;
    const float* sb = src + (long)b * bstride + (long)ch * 64 * HW;
    int t = threadIdx.x;
    #pragma unroll
    for (int dy = 0; dy < 3; dy++) {
        int yy = y + dy - 1;
        for (int i = t; i < 2048; i += 256) {
            int c = i >> 5, x = i & 31;
            float v = -3.4e38f;
            if ((unsigned)yy < 32u) v = sb[c * HW + yy * 32 + x];
            rows[dy][c * 33 + x] = v;
        }
    }
    __syncthreads();
    for (int i = t; i < 2048; i += 256) {
        int c = i >> 5, x = i & 31;
        float m = -3.4e38f;
        #pragma unroll
        for (int dy = 0; dy < 3; dy++)
            #pragma unroll
            for (int dx = -1; dx <= 1; dx++) {
                int xx = x + dx;
                if ((unsigned)xx < 32u) m = fmaxf(m, rows[dy][c * 33 + xx]);
            }
        g_max[((size_t)(st * 64 + b) * 128 + ch * 64 + c) * 1024 + y * 32 + x] = m;
    }
    for (int i = t; i < 2048; i += 256) {
        int x = i >> 6, c = i & 63;
        float v = rows[1][c * 33 + x];
        __nv_bfloat16 hi = __float2bfloat16(v);
        size_t o = (((size_t)(st * 64 + b) * 36 + y + 2) * 36 + x + 2) * 128 + ch * 64 + c;
        g_in[o] = hi;
        g_in[ISZ + o] = __float2bfloat16(v - __bfloat162float(hi));
    }
}

// ---------------- mma.sync GEMM node kernel ----------------
// grid 512 (= 64 b * 8 rowgroups of 4 rows), 256 thr, dyn smem 2*64KB
// D[oc 128][px 128] += sum over 72 stages (18 taps x 2 states x 2 ic-halves), K=64 each.
__global__ __launch_bounds__(256) void gemm_node_kernel(int stA, int stB, int e0, int e1,
                                                        float* __restrict__ out) {
    extern __shared__ char dsm[];
    int t = threadIdx.x;
    int b = blockIdx.x >> 3;
    int y0r = (blockIdx.x & 7) * 4;

    uint32_t base = (s2u(dsm) + 1023u) & ~1023u;

    const int lane = t & 31, wid = t >> 5;
    const int wm = wid & 3;                 // oc block: wm*32
    const int wn = wid >> 2;                // px block: wn*64
    const int lrow = (lane & 7) + ((lane >> 3) & 1) * 8;  // ldmatrix row-in-tile
    const int chalf = lane >> 4;                          // ldmatrix k-half

    float acc[2][8][4];
    #pragma unroll
    for (int mi = 0; mi < 2; mi++)
        #pragma unroll
        for (int ni = 0; ni < 8; ni++)
            #pragma unroll
            for (int j = 0; j < 4; j++) acc[mi][ni][j] = 0.f;

#define STAGE(ITN, BUFB) do {                                                       \
    int it_ = (ITN);                                                                \
    int tap_ = it_ >> 2, ck_ = it_ & 3;                                             \
    int dy_, dx_;                                                                   \
    if (tap_ < 9) { dy_ = tap_ / 3 - 1; dx_ = tap_ % 3 - 1; }                       \
    else { int t2_ = tap_ - 9; dy_ = (t2_ / 3 - 1) * 2; dx_ = (t2_ % 3 - 1) * 2; }  \
    int e_ = (ck_ < 2) ? e0 : e1;                                                   \
    int st_ = (ck_ < 2) ? stA : stB;                                                \
    int ih_ = (ck_ & 1) * 64;                                                       \
    const __nv_bfloat16* wsrc_ = g_wA + ((size_t)(e_ * 18 + tap_) * 128) * 128 + ih_; \
    const __nv_bfloat16* bsrc_ = g_in + ((size_t)(st_ * 64 + b) * 1296) * 128 + ih_;  \
    _Pragma("unroll")                                                               \
    for (int part_ = 0; part_ < 2; part_++) {                                       \
        _Pragma("unroll")                                                           \
        for (int j_ = 0; j_ < 4; j_++) {                                            \
            int idx_ = t + j_ * 256;                                                \
            int row_ = idx_ >> 3, c16_ = idx_ & 7;                                  \
            uint32_t sw_ = (uint32_t)(row_ * 128 + ((c16_ ^ (row_ & 7)) << 4));     \
            cp16((BUFB) + part_ * 16384 + sw_,                                      \
                 wsrc_ + (size_t)part_ * WSZ + row_ * 128 + c16_ * 8);              \
            int yr_ = row_ >> 5, xx_ = row_ & 31;                                   \
            cp16((BUFB) + 32768 + part_ * 16384 + sw_,                              \
                 bsrc_ + (size_t)part_ * ISZ +                                      \
                 ((y0r + yr_ + 2 + dy_) * 36 + (xx_ + 2 + dx_)) * 128 + c16_ * 8);  \
        }                                                                           \
    }                                                                               \
    cp_commit();                                                                    \
} while (0)

    STAGE(0, base);
    STAGE(1, base + 65536);

    for (int it = 0; it < 72; it++) {
        uint32_t buf = base + (uint32_t)(it & 1) * 65536;
        if (it < 71) asm volatile("cp.async.wait_group 1;" ::: "memory");
        else         asm volatile("cp.async.wait_group 0;" ::: "memory");
        __syncthreads();

        #pragma unroll
        for (int kc = 0; kc < 4; kc++) {
            uint32_t ah[2][4], al[2][4], bh[4][4], bl[4][4];
            #pragma unroll
            for (int mi = 0; mi < 2; mi++) {
                int row = wm * 32 + mi * 16 + lrow;
                uint32_t a = buf + (uint32_t)(row * 128 + (((2 * kc + chalf) ^ (row & 7)) << 4));
                ldx4(ah[mi], a);
                ldx4(al[mi], a + 16384);
            }
            #pragma unroll
            for (int pi = 0; pi < 4; pi++) {
                int row = wn * 64 + pi * 16 + lrow;
                uint32_t a = buf + 32768u +
                             (uint32_t)(row * 128 + (((2 * kc + chalf) ^ (row & 7)) << 4));
                ldx4(bh[pi], a);
                ldx4(bl[pi], a + 16384);
            }
            #pragma unroll
            for (int mi = 0; mi < 2; mi++) {
                #pragma unroll
                for (int ni = 0; ni < 8; ni++) {
                    int pi = ni >> 1, sub = ni & 1;
                    mma16816(acc[mi][ni], ah[mi], bh[pi][sub], bh[pi][sub + 2]);
                    mma16816(acc[mi][ni], ah[mi], bl[pi][sub], bl[pi][sub + 2]);
                    mma16816(acc[mi][ni], al[mi], bh[pi][sub], bh[pi][sub + 2]);
                }
            }
        }

        __syncthreads();
        if (it + 2 < 72) STAGE(it + 2, buf);
    }
#undef STAGE

    // epilogue: add max-pool terms, write fp32
    float a4A = g_alpha[e0][4], a4B = g_alpha[e1][4];
    int tq = lane >> 2;
    int tr = (lane & 3) * 2;
    #pragma unroll
    for (int mi = 0; mi < 2; mi++) {
        #pragma unroll
        for (int h = 0; h < 2; h++) {
            int oc = wm * 32 + mi * 16 + tq + h * 8;
            const float* mA = g_max + ((size_t)(stA * 64 + b) * 128 + oc) * 1024 + y0r * 32;
            const float* mB = g_max + ((size_t)(stB * 64 + b) * 128 + oc) * 1024 + y0r * 32;
            float* op = out + ((long)b * OUTC + oc) * HW + y0r * 32;
            #pragma unroll
            for (int ni = 0; ni < 8; ni++) {
                int px = wn * 64 + ni * 8 + tr;
                float v0 = acc[mi][ni][2 * h]     + a4A * mA[px]     + a4B * mB[px];
                float v1 = acc[mi][ni][2 * h + 1] + a4A * mA[px + 1] + a4B * mB[px + 1];
                *(float2*)&op[px] = make_float2(v0, v1);
            }
        }
    }
}

// ---------------- skip copies ----------------
__global__ void copy_skip_kernel(const float* __restrict__ skip, float* __restrict__ out) {
    int idx = blockIdx.x * blockDim.x + threadIdx.x;
    float4 v = ((const float4*)skip)[idx];
    int hw4 = idx & 255;
    int c = (idx >> 8) & 127;
    int n = idx >> 15;
    ((float4*)out)[(long)n * (OUTC * HW / 4) + (512 + c) * (HW / 4) + hw4] = v;
    ((float4*)out)[(long)B * OUTC * HW / 4 + idx] = v;
}

// ---------------- launch ----------------
extern "C" void kernel_launch(void* const* d_in, const int* in_sizes, int n_in,
                              void* d_out, int out_size) {
    const float* input0  = (const float*)d_in[0];
    const float* input1  = (const float*)d_in[1];
    const float* skip    = (const float*)d_in[2];
    const float* w_pre0  = (const float*)d_in[3];
    const float* w_pre1  = (const float*)d_in[4];
    const float* w_conv3 = (const float*)d_in[5];
    const float* w_dil3  = (const float*)d_in[6];
    const float* alphas  = (const float*)d_in[7];
    float* out = (float*)d_out;

    float *s0, *s1;
    cudaGetSymbolAddress((void**)&s0, g_s0);
    cudaGetSymbolAddress((void**)&s1, g_s1);

    softmax_kernel<<<1, 32>>>(alphas);
    prep_w_kernel<<<WSZ / 256, 256>>>(w_conv3, w_dil3);

    const int smem1x1 = (C * WS_STRIDE + C * 64) * sizeof(float);
    cudaFuncSetAttribute(conv1x1_kernel, cudaFuncAttributeMaxDynamicSharedMemorySize, smem1x1);
    conv1x1_kernel<<<1024, 256, smem1x1>>>(input0, w_pre0, s0);
    conv1x1_kernel<<<1024, 256, smem1x1>>>(input1, w_pre1, s1);

    dim3 pgrid(32, 2, 64);
    postprep_kernel<<<pgrid, 256>>>(s0, (long)C * HW, 0);
    postprep_kernel<<<pgrid, 256>>>(s1, (long)C * HW, 1);

    const int gsm = 2 * 65536 + 1024;
    cudaFuncSetAttribute(gemm_node_kernel, cudaFuncAttributeMaxDynamicSharedMemorySize, gsm);

    gemm_node_kernel<<<512, 256, gsm>>>(0, 1, 0, 1, out + 0 * C * HW);
    postprep_kernel<<<pgrid, 256>>>(out + 0 * C * HW, (long)OUTC * HW, 2);
    gemm_node_kernel<<<512, 256, gsm>>>(1, 2, 2, 3, out + 1 * C * HW);
    postprep_kernel<<<pgrid, 256>>>(out + 1 * C * HW, (long)OUTC * HW, 3);
    gemm_node_kernel<<<512, 256, gsm>>>(2, 3, 4, 5, out + 2 * C * HW);
    postprep_kernel<<<pgrid, 256>>>(out + 2 * C * HW, (long)OUTC * HW, 4);
    gemm_node_kernel<<<512, 256, gsm>>>(3, 4, 6, 7, out + 3 * C * HW);

    copy_skip_kernel<<<(B * C * HW / 4) / 256, 256>>>(skip, out);
}

// round 12
// speedup vs baseline: 11.7563x; 2.3876x over previous
#include <cuda_runtime.h>
#include <cuda_fp16.h>
#include <cstdint>

#define B 64
#define C 128
#define HW 1024
#define OUTC 640
#define WS_STRIDE 132
#define WSZ (8*18*128*128)
#define ISZ (5L*64*36*36*128)

typedef unsigned long long u64;

__device__ __forceinline__ u64 pk2(float lo, float hi) {
    u64 r; asm("mov.b64 %0, {%1, %2};" : "=l"(r) : "f"(lo), "f"(hi)); return r;
}
__device__ __forceinline__ void ffma2(u64& d, u64 a, u64 b) {
    asm("fma.rn.f32x2 %0, %1, %2, %0;" : "+l"(d) : "l"(a), "l"(b));
}
__device__ __forceinline__ float2 upk(u64 v) {
    float2 r; asm("mov.b64 {%0, %1}, %2;" : "=f"(r.x), "=f"(r.y) : "l"(v)); return r;
}
__device__ __forceinline__ uint32_t s2u(const void* p) {
    return (uint32_t)__cvta_generic_to_shared(p);
}
__device__ __forceinline__ void cp16(uint32_t s, const void* g) {
    asm volatile("cp.async.cg.shared.global [%0], [%1], 16;" :: "r"(s), "l"(g));
}
__device__ __forceinline__ void cp_commit() { asm volatile("cp.async.commit_group;"); }

__device__ __forceinline__ void ldx4(uint32_t* r, uint32_t a) {
    asm volatile("ldmatrix.sync.aligned.m8n8.x4.shared.b16 {%0,%1,%2,%3}, [%4];"
        : "=r"(r[0]), "=r"(r[1]), "=r"(r[2]), "=r"(r[3]) : "r"(a));
}
__device__ __forceinline__ void mma16816(float* d, const uint32_t* a, uint32_t b0, uint32_t b1) {
    asm volatile("mma.sync.aligned.m16n8k16.row.col.f32.f16.f16.f32 "
        "{%0,%1,%2,%3}, {%4,%5,%6,%7}, {%8,%9}, {%0,%1,%2,%3};"
        : "+f"(d[0]), "+f"(d[1]), "+f"(d[2]), "+f"(d[3])
        : "r"(a[0]), "r"(a[1]), "r"(a[2]), "r"(a[3]), "r"(b0), "r"(b1));
}

// ---------------- device scratch ----------------
__device__ float g_s0[B * C * HW];
__device__ float g_s1[B * C * HW];
__device__ float g_alpha[8][5];
__device__ __half g_wA[WSZ];                 // [e][tap][oc][ic] fp16 folded weights
__device__ __half g_in[ISZ];                 // [st][b][py36][px36][c] fp16, zero halo
__device__ float g_max[5L * 64 * 128 * 1024]; // raw max3x3 per state, NCHW

// ---------------- softmax ----------------
__global__ void softmax_kernel(const float* __restrict__ alphas) {
    int r = threadIdx.x;
    if (r < 8) {
        float m = -3.4e38f;
        #pragma unroll
        for (int j = 0; j < 5; j++) m = fmaxf(m, alphas[r * 5 + j]);
        float e[5], s = 0.f;
        #pragma unroll
        for (int j = 0; j < 5; j++) { e[j] = expf(alphas[r * 5 + j] - m); s += e[j]; }
        float inv = 1.f / s;
        #pragma unroll
        for (int j = 0; j < 5; j++) g_alpha[r][j] = e[j] * inv;
    }
}

// ---------------- weight prep: alpha-scale + identity/avg fold -> fp16 ----------------
__global__ void prep_w_kernel(const float* __restrict__ wc, const float* __restrict__ wd) {
    int idx = blockIdx.x * blockDim.x + threadIdx.x;
    if (idx >= WSZ) return;
    int ic = idx & 127;
    int oc = (idx >> 7) & 127;
    int r = idx >> 14;               // 0..143
    int tap = r % 18, e = r / 18;
    float v;
    if (tap < 9) {
        v = g_alpha[e][1] * wc[((e * 128 + oc) * 128 + ic) * 9 + tap];
        if (oc == ic) {
            v += g_alpha[e][3] * (1.f / 9.f);
            if (tap == 4) v += g_alpha[e][0];
        }
    } else {
        v = g_alpha[e][2] * wd[((e * 128 + oc) * 128 + ic) * 9 + tap - 9];
    }
    g_wA[idx] = __float2half_rn(v);
}

// ---------------- 1x1 conv (FFMA2 fp32, exact) ----------------
__global__ __launch_bounds__(256) void conv1x1_kernel(const float* __restrict__ in,
                                                      const float* __restrict__ w,
                                                      float* __restrict__ out) {
    extern __shared__ float sm[];
    float* ws = sm;
    float* ins = sm + C * WS_STRIDE;
    int t = threadIdx.x;
    int n = blockIdx.x >> 4;
    int hw0 = (blockIdx.x & 15) << 6;

    for (int i = t; i < C * C; i += 256) {
        int oc = i >> 7, ic = i & 127;
        ws[ic * WS_STRIDE + oc] = w[i];
    }
    const float4* inb = (const float4*)(in + (long)n * C * HW + hw0);
    float4* insv = (float4*)ins;
    for (int i = t; i < C * 16; i += 256) {
        int ic = i >> 4, p4 = i & 15;
        insv[ic * 16 + p4] = inb[ic * (HW / 4) + p4];
    }
    __syncthreads();

    int pg = t & 15, og = t >> 4;
    int ocb = og * 8;
    u64 acc2[4][4];
    #pragma unroll
    for (int k = 0; k < 4; k++)
        #pragma unroll
        for (int j = 0; j < 4; j++) acc2[k][j] = 0ull;

    for (int ic = 0; ic < C; ic++) {
        float4 iv = *(const float4*)&ins[ic * 64 + pg * 4];
        float4 wa = *(const float4*)&ws[ic * WS_STRIDE + ocb];
        float4 wb = *(const float4*)&ws[ic * WS_STRIDE + ocb + 4];
        u64 w0 = pk2(wa.x, wa.y), w1 = pk2(wa.z, wa.w);
        u64 w2 = pk2(wb.x, wb.y), w3 = pk2(wb.z, wb.w);
        float xv[4] = {iv.x, iv.y, iv.z, iv.w};
        #pragma unroll
        for (int k = 0; k < 4; k++) {
            u64 xd = pk2(xv[k], xv[k]);
            ffma2(acc2[k][0], xd, w0);
            ffma2(acc2[k][1], xd, w1);
            ffma2(acc2[k][2], xd, w2);
            ffma2(acc2[k][3], xd, w3);
        }
    }

    float* ob = out + (long)n * C * HW + hw0 + pg * 4;
    #pragma unroll
    for (int jp = 0; jp < 4; jp++) {
        float2 v0 = upk(acc2[0][jp]), v1 = upk(acc2[1][jp]);
        float2 v2 = upk(acc2[2][jp]), v3 = upk(acc2[3][jp]);
        *(float4*)&ob[(ocb + 2 * jp) * HW]     = make_float4(v0.x, v1.x, v2.x, v3.x);
        *(float4*)&ob[(ocb + 2 * jp + 1) * HW] = make_float4(v0.y, v1.y, v2.y, v3.y);
    }
}

// ---------------- postprep: fp32 NCHW state -> padded NHWC fp16 + raw max3x3 ----------------
__global__ __launch_bounds__(256) void postprep_kernel(const float* __restrict__ src,
                                                       long bstride, int st) {
    __shared__ float rows[3][64 * 33];
    int y = blockIdx.x, ch = blockIdx.y, b = blockIdx.z;
    const float* sb = src + (long)b * bstride + (long)ch * 64 * HW;
    int t = threadIdx.x;
    #pragma unroll
    for (int dy = 0; dy < 3; dy++) {
        int yy = y + dy - 1;
        for (int i = t; i < 2048; i += 256) {
            int c = i >> 5, x = i & 31;
            float v = -3.4e38f;
            if ((unsigned)yy < 32u) v = sb[c * HW + yy * 32 + x];
            rows[dy][c * 33 + x] = v;
        }
    }
    __syncthreads();
    for (int i = t; i < 2048; i += 256) {
        int c = i >> 5, x = i & 31;
        float m = -3.4e38f;
        #pragma unroll
        for (int dy = 0; dy < 3; dy++)
            #pragma unroll
            for (int dx = -1; dx <= 1; dx++) {
                int xx = x + dx;
                if ((unsigned)xx < 32u) m = fmaxf(m, rows[dy][c * 33 + xx]);
            }
        g_max[((size_t)(st * 64 + b) * 128 + ch * 64 + c) * 1024 + y * 32 + x] = m;
    }
    for (int i = t; i < 2048; i += 256) {
        int x = i >> 6, c = i & 63;
        float v = rows[1][c * 33 + x];
        size_t o = (((size_t)(st * 64 + b) * 36 + y + 2) * 36 + x + 2) * 128 + ch * 64 + c;
        g_in[o] = __float2half_rn(v);
    }
}

// ---------------- mma.sync fp16 GEMM node kernel ----------------
// grid 256 (= 64 b * 4 rowgroups of 8 rows), 256 thr, dyn smem 2*96KB
// D[oc 128][px 256] = sum over 36 stages (18 taps x 2 inputs), K=128 each.
__global__ __launch_bounds__(256) void gemm_node_kernel(int stA, int stB, int e0, int e1,
                                                        float* __restrict__ out) {
    extern __shared__ char dsm[];
    int t = threadIdx.x;
    int b = blockIdx.x >> 2;
    int y0r = (blockIdx.x & 3) * 8;

    uint32_t base = (s2u(dsm) + 1023u) & ~1023u;

    const int lane = t & 31, wid = t >> 5;
    const int wm = wid & 3;                 // oc block: wm*32
    const int wn = wid >> 2;                // px block: wn*128
    const int lrow = (lane & 7) + ((lane >> 3) & 1) * 8;
    const int chalf = lane >> 4;

    float acc[2][16][4];
    #pragma unroll
    for (int mi = 0; mi < 2; mi++)
        #pragma unroll
        for (int ni = 0; ni < 16; ni++)
            #pragma unroll
            for (int j = 0; j < 4; j++) acc[mi][ni][j] = 0.f;

#define STAGE(ITN, BUFB) do {                                                       \
    int it_ = (ITN);                                                                \
    int inp_ = it_ & 1, tap_ = it_ >> 1;                                            \
    int dy_, dx_;                                                                   \
    if (tap_ < 9) { dy_ = tap_ / 3 - 1; dx_ = tap_ % 3 - 1; }                       \
    else { int t2_ = tap_ - 9; dy_ = (t2_ / 3 - 1) * 2; dx_ = (t2_ % 3 - 1) * 2; }  \
    int e_ = inp_ ? e1 : e0;                                                        \
    int st_ = inp_ ? stB : stA;                                                     \
    const __half* wsrc_ = g_wA + ((size_t)(e_ * 18 + tap_) << 14);                  \
    const __half* bsrc_ = g_in + ((size_t)(st_ * 64 + b) * 1296) * 128;             \
    _Pragma("unroll")                                                               \
    for (int j_ = 0; j_ < 8; j_++) {                                                \
        int idx_ = t + j_ * 256;                                                    \
        int row_ = idx_ >> 4, c16_ = idx_ & 15;                                     \
        cp16((BUFB) + (uint32_t)(row_ * 256 + ((c16_ ^ (row_ & 7)) << 4)),          \
             wsrc_ + row_ * 128 + c16_ * 8);                                        \
    }                                                                               \
    _Pragma("unroll")                                                               \
    for (int j_ = 0; j_ < 16; j_++) {                                               \
        int idx_ = t + j_ * 256;                                                    \
        int row_ = idx_ >> 4, c16_ = idx_ & 15;                                     \
        int yr_ = row_ >> 5, xx_ = row_ & 31;                                       \
        cp16((BUFB) + 32768u + (uint32_t)(row_ * 256 + ((c16_ ^ (row_ & 7)) << 4)), \
             bsrc_ + ((y0r + yr_ + 2 + dy_) * 36 + (xx_ + 2 + dx_)) * 128 + c16_ * 8); \
    }                                                                               \
    cp_commit();                                                                    \
} while (0)

    STAGE(0, base);
    STAGE(1, base + 98304);

    for (int it = 0; it < 36; it++) {
        uint32_t buf = base + (uint32_t)(it & 1) * 98304;
        if (it < 35) asm volatile("cp.async.wait_group 1;" ::: "memory");
        else         asm volatile("cp.async.wait_group 0;" ::: "memory");
        __syncthreads();

        #pragma unroll
        for (int kc = 0; kc < 8; kc++) {
            uint32_t af[2][4];
            #pragma unroll
            for (int mi = 0; mi < 2; mi++) {
                int row = wm * 32 + mi * 16 + lrow;
                ldx4(af[mi], buf + (uint32_t)(row * 256 + (((2 * kc + chalf) ^ (row & 7)) << 4)));
            }
            #pragma unroll
            for (int pi = 0; pi < 8; pi++) {
                uint32_t bf[4];
                int row = wn * 128 + pi * 16 + lrow;
                ldx4(bf, buf + 32768u +
                         (uint32_t)(row * 256 + (((2 * kc + chalf) ^ (row & 7)) << 4)));
                #pragma unroll
                for (int mi = 0; mi < 2; mi++) {
                    mma16816(acc[mi][2 * pi],     af[mi], bf[0], bf[2]);
                    mma16816(acc[mi][2 * pi + 1], af[mi], bf[1], bf[3]);
                }
            }
        }

        __syncthreads();
        if (it + 2 < 36) STAGE(it + 2, buf);
    }
#undef STAGE

    // epilogue: add max-pool terms, write fp32
    float a4A = g_alpha[e0][4], a4B = g_alpha[e1][4];
    int tq = lane >> 2;
    int tr = (lane & 3) * 2;
    #pragma unroll
    for (int mi = 0; mi < 2; mi++) {
        #pragma unroll
        for (int h = 0; h < 2; h++) {
            int oc = wm * 32 + mi * 16 + tq + h * 8;
            const float* mA = g_max + ((size_t)(stA * 64 + b) * 128 + oc) * 1024 + y0r * 32;
            const float* mB = g_max + ((size_t)(stB * 64 + b) * 128 + oc) * 1024 + y0r * 32;
            float* op = out + ((long)b * OUTC + oc) * HW + y0r * 32;
            #pragma unroll
            for (int ni = 0; ni < 16; ni++) {
                int px = wn * 128 + ni * 8 + tr;
                float v0 = acc[mi][ni][2 * h]     + a4A * mA[px]     + a4B * mB[px];
                float v1 = acc[mi][ni][2 * h + 1] + a4A * mA[px + 1] + a4B * mB[px + 1];
                *(float2*)&op[px] = make_float2(v0, v1);
            }
        }
    }
}

// ---------------- skip copies ----------------
__global__ void copy_skip_kernel(const float* __restrict__ skip, float* __restrict__ out) {
    int idx = blockIdx.x * blockDim.x + threadIdx.x;
    float4 v = ((const float4*)skip)[idx];
    int hw4 = idx & 255;
    int c = (idx >> 8) & 127;
    int n = idx >> 15;
    ((float4*)out)[(long)n * (OUTC * HW / 4) + (512 + c) * (HW / 4) + hw4] = v;
    ((float4*)out)[(long)B * OUTC * HW / 4 + idx] = v;
}

// ---------------- launch ----------------
extern "C" void kernel_launch(void* const* d_in, const int* in_sizes, int n_in,
                              void* d_out, int out_size) {
    const float* input0  = (const float*)d_in[0];
    const float* input1  = (const float*)d_in[1];
    const float* skip    = (const float*)d_in[2];
    const float* w_pre0  = (const float*)d_in[3];
    const float* w_pre1  = (const float*)d_in[4];
    const float* w_conv3 = (const float*)d_in[5];
    const float* w_dil3  = (const float*)d_in[6];
    const float* alphas  = (const float*)d_in[7];
    float* out = (float*)d_out;

    float *s0, *s1;
    cudaGetSymbolAddress((void**)&s0, g_s0);
    cudaGetSymbolAddress((void**)&s1, g_s1);

    softmax_kernel<<<1, 32>>>(alphas);
    prep_w_kernel<<<WSZ / 256, 256>>>(w_conv3, w_dil3);

    const int smem1x1 = (C * WS_STRIDE + C * 64) * sizeof(float);
    cudaFuncSetAttribute(conv1x1_kernel, cudaFuncAttributeMaxDynamicSharedMemorySize, smem1x1);
    conv1x1_kernel<<<1024, 256, smem1x1>>>(input0, w_pre0, s0);
    conv1x1_kernel<<<1024, 256, smem1x1>>>(input1, w_pre1, s1);

    dim3 pgrid(32, 2, 64);
    postprep_kernel<<<pgrid, 256>>>(s0, (long)C * HW, 0);
    postprep_kernel<<<pgrid, 256>>>(s1, (long)C * HW, 1);

    const int gsm = 2 * 98304 + 1024;
    cudaFuncSetAttribute(gemm_node_kernel, cudaFuncAttributeMaxDynamicSharedMemorySize, gsm);

    gemm_node_kernel<<<256, 256, gsm>>>(0, 1, 0, 1, out + 0 * C * HW);
    postprep_kernel<<<pgrid, 256>>>(out + 0 * C * HW, (long)OUTC * HW, 2);
    gemm_node_kernel<<<256, 256, gsm>>>(1, 2, 2, 3, out + 1 * C * HW);
    postprep_kernel<<<pgrid, 256>>>(out + 1 * C * HW, (long)OUTC * HW, 3);
    gemm_node_kernel<<<256, 256, gsm>>>(2, 3, 4, 5, out + 2 * C * HW);
    postprep_kernel<<<pgrid, 256>>>(out + 2 * C * HW, (long)OUTC * HW, 4);
    gemm_node_kernel<<<256, 256, gsm>>>(3, 4, 6, 7, out + 3 * C * HW);

    copy_skip_kernel<<<(B * C * HW / 4) / 256, 256>>>(skip, out);
}

// round 13
// speedup vs baseline: 12.9752x; 1.1037x over previous
#include <cuda_runtime.h>
#include <cuda_fp16.h>
#include <cstdint>

#define B 64
#define C 128
#define HW 1024
#define OUTC 640
#define WSZ (8*18*128*128)
#define ISZ (5L*64*36*36*128)

typedef unsigned long long u64;

__device__ __forceinline__ uint32_t s2u(const void* p) {
    return (uint32_t)__cvta_generic_to_shared(p);
}
__device__ __forceinline__ void cp16(uint32_t s, const void* g) {
    asm volatile("cp.async.cg.shared.global [%0], [%1], 16;" :: "r"(s), "l"(g));
}
__device__ __forceinline__ void cp_commit() { asm volatile("cp.async.commit_group;"); }

__device__ __forceinline__ void ldx4(uint32_t* r, uint32_t a) {
    asm volatile("ldmatrix.sync.aligned.m8n8.x4.shared.b16 {%0,%1,%2,%3}, [%4];"
        : "=r"(r[0]), "=r"(r[1]), "=r"(r[2]), "=r"(r[3]) : "r"(a));
}
__device__ __forceinline__ void mma16816(float* d, const uint32_t* a, uint32_t b0, uint32_t b1) {
    asm volatile("mma.sync.aligned.m16n8k16.row.col.f32.f16.f16.f32 "
        "{%0,%1,%2,%3}, {%4,%5,%6,%7}, {%8,%9}, {%0,%1,%2,%3};"
        : "+f"(d[0]), "+f"(d[1]), "+f"(d[2]), "+f"(d[3])
        : "r"(a[0]), "r"(a[1]), "r"(a[2]), "r"(a[3]), "r"(b0), "r"(b1));
}

// ---------------- device scratch ----------------
__device__ float g_alpha[8][5];
__device__ __half g_wA[WSZ];                  // [e][tap][oc][ic] fp16 folded 3x3/dil weights
__device__ __half g_w1[2 * 128 * 128];        // [st][oc][ic] fp16 1x1 weights
__device__ __half g_x[2L * 64 * 1024 * 128];  // [st][b][px][c] fp16 NHWC inputs (for 1x1 conv)
__device__ __half g_in[ISZ];                  // [st][b][py36*px36][c] fp16 states, zero halo
__device__ float g_max[5L * 64 * 128 * 1024]; // max3x3 per state, NCHW fp32

// ---------------- softmax ----------------
__global__ void softmax_kernel(const float* __restrict__ alphas) {
    int r = threadIdx.x;
    if (r < 8) {
        float m = -3.4e38f;
        #pragma unroll
        for (int j = 0; j < 5; j++) m = fmaxf(m, alphas[r * 5 + j]);
        float e[5], s = 0.f;
        #pragma unroll
        for (int j = 0; j < 5; j++) { e[j] = expf(alphas[r * 5 + j] - m); s += e[j]; }
        float inv = 1.f / s;
        #pragma unroll
        for (int j = 0; j < 5; j++) g_alpha[r][j] = e[j] * inv;
    }
}

// ---------------- weight prep: alpha-scale + identity/avg fold -> fp16 ----------------
__global__ void prep_w_kernel(const float* __restrict__ wc, const float* __restrict__ wd) {
    int idx = blockIdx.x * blockDim.x + threadIdx.x;
    if (idx >= WSZ) return;
    int ic = idx & 127;
    int oc = (idx >> 7) & 127;
    int r = idx >> 14;
    int tap = r % 18, e = r / 18;
    float v;
    if (tap < 9) {
        v = g_alpha[e][1] * wc[((e * 128 + oc) * 128 + ic) * 9 + tap];
        if (oc == ic) {
            v += g_alpha[e][3] * (1.f / 9.f);
            if (tap == 4) v += g_alpha[e][0];
        }
    } else {
        v = g_alpha[e][2] * wd[((e * 128 + oc) * 128 + ic) * 9 + tap - 9];
    }
    g_wA[idx] = __float2half_rn(v);
}

__global__ void prep_w1_kernel(const float* __restrict__ w0, const float* __restrict__ w1) {
    int idx = blockIdx.x * blockDim.x + threadIdx.x;
    if (idx >= 32768) return;
    const float* s = (idx < 16384) ? w0 : w1;
    g_w1[idx] = __float2half_rn(s[idx & 16383]);
}

// ---------------- input transpose: NCHW fp32 -> NHWC fp16 ----------------
// grid (8 px-chunks of 128, 64 b, 2 st), 256 thr
__global__ __launch_bounds__(256) void in_tr_kernel(const float* __restrict__ in0,
                                                    const float* __restrict__ in1) {
    __shared__ __half s_tr[128][130];
    int t = threadIdx.x;
    int px0 = blockIdx.x * 128, b = blockIdx.y, st = blockIdx.z;
    const float* src = st ? in1 : in0;
    #pragma unroll
    for (int i = 0; i < 16; i++) {
        int idx = t + i * 256;            // 4096 float4
        int c = idx >> 5, f4 = idx & 31;
        float4 v = *(const float4*)(src + ((size_t)(b * 128 + c)) * 1024 + px0 + f4 * 4);
        s_tr[f4 * 4 + 0][c] = __float2half_rn(v.x);
        s_tr[f4 * 4 + 1][c] = __float2half_rn(v.y);
        s_tr[f4 * 4 + 2][c] = __float2half_rn(v.z);
        s_tr[f4 * 4 + 3][c] = __float2half_rn(v.w);
    }
    __syncthreads();
    #pragma unroll
    for (int k = 0; k < 8; k++) {
        int px = (t >> 4) + k * 16, ch = t & 15;
        const __half2* sp = (const __half2*)&s_tr[px][ch * 8];
        uint4 v;
        v.x = *(const uint32_t*)&sp[0]; v.y = *(const uint32_t*)&sp[1];
        v.z = *(const uint32_t*)&sp[2]; v.w = *(const uint32_t*)&sp[3];
        *(uint4*)(g_x + ((size_t)(st * 64 + b) * 1024 + px0 + px) * 128 + ch * 8) = v;
    }
}

// ---------------- 1x1 conv as fp16 GEMM: D[128oc][256px], K=128; writes g_in padded NHWC ----
// grid (4 pxgroups, 64 b, 2 st), 256 thr, dyn smem 97KB
__global__ __launch_bounds__(256) void pre_gemm_kernel() {
    extern __shared__ char dsm[];
    int t = threadIdx.x;
    int pxg = blockIdx.x, b = blockIdx.y, st = blockIdx.z;
    uint32_t base = (s2u(dsm) + 1023u) & ~1023u;

    const int lane = t & 31, wid = t >> 5;
    const int wm = wid & 3, wn = wid >> 2;
    const int lrow = (lane & 7) + ((lane >> 3) & 1) * 8;
    const int chalf = lane >> 4;

    // stage A (weights 128x128) + B (256px x 128)
    #pragma unroll
    for (int j = 0; j < 8; j++) {
        int idx = t + j * 256;             // 2048 A
        int row = idx >> 4, c16 = idx & 15;
        cp16(base + (uint32_t)(row * 256 + ((c16 ^ (row & 7)) << 4)),
             g_w1 + (st << 14) + row * 128 + c16 * 8);
    }
    #pragma unroll
    for (int j = 0; j < 16; j++) {
        int idx = t + j * 256;             // 4096 B
        int row = idx >> 4, c16 = idx & 15;
        cp16(base + 32768u + (uint32_t)(row * 256 + ((c16 ^ (row & 7)) << 4)),
             g_x + ((size_t)(st * 64 + b) * 1024 + pxg * 256 + row) * 128 + c16 * 8);
    }
    cp_commit();
    asm volatile("cp.async.wait_group 0;" ::: "memory");
    __syncthreads();

    float acc[2][16][4];
    #pragma unroll
    for (int mi = 0; mi < 2; mi++)
        #pragma unroll
        for (int ni = 0; ni < 16; ni++)
            #pragma unroll
            for (int j = 0; j < 4; j++) acc[mi][ni][j] = 0.f;

    #pragma unroll
    for (int kc = 0; kc < 8; kc++) {
        uint32_t af[2][4];
        #pragma unroll
        for (int mi = 0; mi < 2; mi++) {
            int row = wm * 32 + mi * 16 + lrow;
            ldx4(af[mi], base + (uint32_t)(row * 256 + (((2 * kc + chalf) ^ (row & 7)) << 4)));
        }
        #pragma unroll
        for (int pi = 0; pi < 8; pi++) {
            uint32_t bf[4];
            int row = wn * 128 + pi * 16 + lrow;
            ldx4(bf, base + 32768u +
                     (uint32_t)(row * 256 + (((2 * kc + chalf) ^ (row & 7)) << 4)));
            #pragma unroll
            for (int mi = 0; mi < 2; mi++) {
                mma16816(acc[mi][2 * pi],     af[mi], bf[0], bf[2]);
                mma16816(acc[mi][2 * pi + 1], af[mi], bf[1], bf[3]);
            }
        }
    }
    __syncthreads();

    // transpose via smem -> g_in padded NHWC
    __half* s_t = (__half*)(dsm + ((1023 + 0) & ~1023));
    {
        uint32_t off = base - s2u(dsm);
        s_t = (__half*)(dsm + off);
    }
    int tq = lane >> 2, tr = (lane & 3) * 2;
    #pragma unroll
    for (int mi = 0; mi < 2; mi++)
        #pragma unroll
        for (int h = 0; h < 2; h++) {
            int oc = wm * 32 + mi * 16 + tq + h * 8;
            #pragma unroll
            for (int ni = 0; ni < 16; ni++) {
                int px = wn * 128 + ni * 8 + tr;
                s_t[px * 136 + oc]       = __float2half_rn(acc[mi][ni][2 * h]);
                s_t[(px + 1) * 136 + oc] = __float2half_rn(acc[mi][ni][2 * h + 1]);
            }
        }
    __syncthreads();
    #pragma unroll
    for (int k = 0; k < 16; k++) {
        int px = (t >> 4) + k * 16, ch = t & 15;
        uint4 v = *(const uint4*)&s_t[px * 136 + ch * 8];
        int y = pxg * 8 + (px >> 5), xx = px & 31;
        *(uint4*)(g_in + ((size_t)(st * 64 + b) * 1296 + (y + 2) * 36 + xx + 2) * 128 + ch * 8) = v;
    }
}

// ---------------- separable 3x3 max pool: g_in fp16 NHWC -> g_max fp32 NCHW ----------------
// grid (4 ygroups, 64 b), 256 thr
__device__ __forceinline__ void rowmax3(const __half* bp, int ry, int x, __half2* h,
                                        __half2 NINF) {
    if ((unsigned)ry < 32u) {
        __half2 m[4], l[4], r[4];
        *(uint4*)m = *(const uint4*)(bp + ((ry + 2) * 36 + x + 2) * 128);
        if (x > 0) *(uint4*)l = *(const uint4*)(bp + ((ry + 2) * 36 + x + 1) * 128);
        else { l[0] = l[1] = l[2] = l[3] = NINF; }
        if (x < 31) *(uint4*)r = *(const uint4*)(bp + ((ry + 2) * 36 + x + 3) * 128);
        else { r[0] = r[1] = r[2] = r[3] = NINF; }
        #pragma unroll
        for (int j = 0; j < 4; j++) h[j] = __hmax2(__hmax2(l[j], m[j]), r[j]);
    } else {
        h[0] = h[1] = h[2] = h[3] = NINF;
    }
}

__global__ __launch_bounds__(256) void max_kernel(int st) {
    int t = threadIdx.x;
    int x = t & 31, cg = t >> 5;
    int b = blockIdx.y, y0 = blockIdx.x * 8;
    const __half2 NINF = __half2half2(__ushort_as_half(0xFBFFu));
    #pragma unroll
    for (int hf = 0; hf < 2; hf++) {
        int c8 = (cg + hf * 8) * 8;
        const __half* bp = g_in + ((size_t)(st * 64 + b) * 1296) * 128 + c8;
        float* gmb = g_max + ((size_t)(st * 64 + b) * 128 + c8) * 1024 + x;
        __half2 a[4], bq[4], cq[4];
        rowmax3(bp, y0 - 1, x, a, NINF);
        rowmax3(bp, y0, x, bq, NINF);
        #pragma unroll
        for (int i = 0; i < 8; i++) {
            rowmax3(bp, y0 + i + 1, x, cq, NINF);
            int yo = (y0 + i) * 32;
            #pragma unroll
            for (int j = 0; j < 4; j++) {
                __half2 o = __hmax2(__hmax2(a[j], bq[j]), cq[j]);
                float2 f = __half22float2(o);
                gmb[(2 * j) * 1024 + yo]     = f.x;
                gmb[(2 * j + 1) * 1024 + yo] = f.y;
                a[j] = bq[j]; bq[j] = cq[j];
            }
        }
    }
}

// ---------------- mma.sync fp16 GEMM node kernel ----------------
// grid 256 (= 64 b * 4 rowgroups of 8 rows), 256 thr, dyn smem 2*96KB
__global__ __launch_bounds__(256) void gemm_node_kernel(int stA, int stB, int e0, int e1,
                                                        int stOut, float* __restrict__ out) {
    extern __shared__ char dsm[];
    int t = threadIdx.x;
    int b = blockIdx.x >> 2;
    int y0r = (blockIdx.x & 3) * 8;

    uint32_t base = (s2u(dsm) + 1023u) & ~1023u;

    const int lane = t & 31, wid = t >> 5;
    const int wm = wid & 3;
    const int wn = wid >> 2;
    const int lrow = (lane & 7) + ((lane >> 3) & 1) * 8;
    const int chalf = lane >> 4;

    float acc[2][16][4];
    #pragma unroll
    for (int mi = 0; mi < 2; mi++)
        #pragma unroll
        for (int ni = 0; ni < 16; ni++)
            #pragma unroll
            for (int j = 0; j < 4; j++) acc[mi][ni][j] = 0.f;

#define STAGE(ITN, BUFB) do {                                                       \
    int it_ = (ITN);                                                                \
    int inp_ = it_ & 1, tap_ = it_ >> 1;                                            \
    int dy_, dx_;                                                                   \
    if (tap_ < 9) { dy_ = tap_ / 3 - 1; dx_ = tap_ % 3 - 1; }                       \
    else { int t2_ = tap_ - 9; dy_ = (t2_ / 3 - 1) * 2; dx_ = (t2_ % 3 - 1) * 2; }  \
    int e_ = inp_ ? e1 : e0;                                                        \
    int st_ = inp_ ? stB : stA;                                                     \
    const __half* wsrc_ = g_wA + ((size_t)(e_ * 18 + tap_) << 14);                  \
    const __half* bsrc_ = g_in + ((size_t)(st_ * 64 + b) * 1296) * 128;             \
    _Pragma("unroll")                                                               \
    for (int j_ = 0; j_ < 8; j_++) {                                                \
        int idx_ = t + j_ * 256;                                                    \
        int row_ = idx_ >> 4, c16_ = idx_ & 15;                                     \
        cp16((BUFB) + (uint32_t)(row_ * 256 + ((c16_ ^ (row_ & 7)) << 4)),          \
             wsrc_ + row_ * 128 + c16_ * 8);                                        \
    }                                                                               \
    _Pragma("unroll")                                                               \
    for (int j_ = 0; j_ < 16; j_++) {                                               \
        int idx_ = t + j_ * 256;                                                    \
        int row_ = idx_ >> 4, c16_ = idx_ & 15;                                     \
        int yr_ = row_ >> 5, xx_ = row_ & 31;                                       \
        cp16((BUFB) + 32768u + (uint32_t)(row_ * 256 + ((c16_ ^ (row_ & 7)) << 4)), \
             bsrc_ + ((y0r + yr_ + 2 + dy_) * 36 + (xx_ + 2 + dx_)) * 128 + c16_ * 8); \
    }                                                                               \
    cp_commit();                                                                    \
} while (0)

    STAGE(0, base);
    STAGE(1, base + 98304);

    for (int it = 0; it < 36; it++) {
        uint32_t buf = base + (uint32_t)(it & 1) * 98304;
        if (it < 35) asm volatile("cp.async.wait_group 1;" ::: "memory");
        else         asm volatile("cp.async.wait_group 0;" ::: "memory");
        __syncthreads();

        #pragma unroll
        for (int kc = 0; kc < 8; kc++) {
            uint32_t af[2][4];
            #pragma unroll
            for (int mi = 0; mi < 2; mi++) {
                int row = wm * 32 + mi * 16 + lrow;
                ldx4(af[mi], buf + (uint32_t)(row * 256 + (((2 * kc + chalf) ^ (row & 7)) << 4)));
            }
            #pragma unroll
            for (int pi = 0; pi < 8; pi++) {
                uint32_t bf[4];
                int row = wn * 128 + pi * 16 + lrow;
                ldx4(bf, buf + 32768u +
                         (uint32_t)(row * 256 + (((2 * kc + chalf) ^ (row & 7)) << 4)));
                #pragma unroll
                for (int mi = 0; mi < 2; mi++) {
                    mma16816(acc[mi][2 * pi],     af[mi], bf[0], bf[2]);
                    mma16816(acc[mi][2 * pi + 1], af[mi], bf[1], bf[3]);
                }
            }
        }

        __syncthreads();
        if (it + 2 < 36) STAGE(it + 2, buf);
    }
#undef STAGE

    // epilogue: add max-pool terms, write fp32 out (+ fp16 state via smem transpose)
    float a4A = g_alpha[e0][4], a4B = g_alpha[e1][4];
    __half* s_t = (__half*)dsm + (base - s2u(dsm)) / 2;
    int tq = lane >> 2;
    int tr = (lane & 3) * 2;
    #pragma unroll
    for (int mi = 0; mi < 2; mi++) {
        #pragma unroll
        for (int h = 0; h < 2; h++) {
            int oc = wm * 32 + mi * 16 + tq + h * 8;
            const float* mA = g_max + ((size_t)(stA * 64 + b) * 128 + oc) * 1024 + y0r * 32;
            const float* mB = g_max + ((size_t)(stB * 64 + b) * 128 + oc) * 1024 + y0r * 32;
            float* op = out + ((long)b * OUTC + oc) * HW + y0r * 32;
            #pragma unroll
            for (int ni = 0; ni < 16; ni++) {
                int px = wn * 128 + ni * 8 + tr;
                float v0 = acc[mi][ni][2 * h]     + a4A * mA[px]     + a4B * mB[px];
                float v1 = acc[mi][ni][2 * h + 1] + a4A * mA[px + 1] + a4B * mB[px + 1];
                *(float2*)&op[px] = make_float2(v0, v1);
                if (stOut >= 0) {
                    s_t[px * 136 + oc]       = __float2half_rn(v0);
                    s_t[(px + 1) * 136 + oc] = __float2half_rn(v1);
                }
            }
        }
    }
    if (stOut >= 0) {
        __syncthreads();
        #pragma unroll
        for (int k = 0; k < 16; k++) {
            int px = (t >> 4) + k * 16, ch = t & 15;
            uint4 v = *(const uint4*)&s_t[px * 136 + ch * 8];
            int y = y0r + (px >> 5), xx = px & 31;
            *(uint4*)(g_in + ((size_t)(stOut * 64 + b) * 1296 + (y + 2) * 36 + xx + 2) * 128
                      + ch * 8) = v;
        }
    }
}

// ---------------- skip copies ----------------
__global__ void copy_skip_kernel(const float* __restrict__ skip, float* __restrict__ out) {
    int idx = blockIdx.x * blockDim.x + threadIdx.x;
    float4 v = ((const float4*)skip)[idx];
    int hw4 = idx & 255;
    int c = (idx >> 8) & 127;
    int n = idx >> 15;
    ((float4*)out)[(long)n * (OUTC * HW / 4) + (512 + c) * (HW / 4) + hw4] = v;
    ((float4*)out)[(long)B * OUTC * HW / 4 + idx] = v;
}

// ---------------- launch ----------------
extern "C" void kernel_launch(void* const* d_in, const int* in_sizes, int n_in,
                              void* d_out, int out_size) {
    const float* input0  = (const float*)d_in[0];
    const float* input1  = (const float*)d_in[1];
    const float* skip    = (const float*)d_in[2];
    const float* w_pre0  = (const float*)d_in[3];
    const float* w_pre1  = (const float*)d_in[4];
    const float* w_conv3 = (const float*)d_in[5];
    const float* w_dil3  = (const float*)d_in[6];
    const float* alphas  = (const float*)d_in[7];
    float* out = (float*)d_out;

    softmax_kernel<<<1, 32>>>(alphas);
    prep_w_kernel<<<WSZ / 256, 256>>>(w_conv3, w_dil3);
    prep_w1_kernel<<<128, 256>>>(w_pre0, w_pre1);
    in_tr_kernel<<<dim3(8, 64, 2), 256>>>(input0, input1);

    const int psm = 98304 + 1024;
    cudaFuncSetAttribute(pre_gemm_kernel, cudaFuncAttributeMaxDynamicSharedMemorySize, psm);
    pre_gemm_kernel<<<dim3(4, 64, 2), 256, psm>>>();

    dim3 mgrid(4, 64);
    max_kernel<<<mgrid, 256>>>(0);
    max_kernel<<<mgrid, 256>>>(1);

    const int gsm = 2 * 98304 + 1024;
    cudaFuncSetAttribute(gemm_node_kernel, cudaFuncAttributeMaxDynamicSharedMemorySize, gsm);

    gemm_node_kernel<<<256, 256, gsm>>>(0, 1, 0, 1, 2, out + 0 * C * HW);
    max_kernel<<<mgrid, 256>>>(2);
    gemm_node_kernel<<<256, 256, gsm>>>(1, 2, 2, 3, 3, out + 1 * C * HW);
    max_kernel<<<mgrid, 256>>>(3);
    gemm_node_kernel<<<256, 256, gsm>>>(2, 3, 4, 5, 4, out + 2 * C * HW);
    max_kernel<<<mgrid, 256>>>(4);
    gemm_node_kernel<<<256, 256, gsm>>>(3, 4, 6, 7, -1, out + 3 * C * HW);

    copy_skip_kernel<<<(B * C * HW / 4) / 256, 256>>>(skip, out);
}

// round 14
// speedup vs baseline: 13.4767x; 1.0387x over previous
#include <cuda_runtime.h>
#include <cuda_fp16.h>
#include <cstdint>

#define B 64
#define C 128
#define HW 1024
#define OUTC 640
#define WSZ (8*18*128*128)
#define ISZ (5L*64*36*36*128)
#define ACT_BYTES (12*36*256)

typedef unsigned long long u64;

__device__ __forceinline__ uint32_t s2u(const void* p) {
    return (uint32_t)__cvta_generic_to_shared(p);
}
__device__ __forceinline__ void cp16(uint32_t s, const void* g) {
    asm volatile("cp.async.cg.shared.global [%0], [%1], 16;" :: "r"(s), "l"(g));
}
__device__ __forceinline__ void cp_commit() { asm volatile("cp.async.commit_group;"); }

__device__ __forceinline__ void ldx4(uint32_t* r, uint32_t a) {
    asm volatile("ldmatrix.sync.aligned.m8n8.x4.shared.b16 {%0,%1,%2,%3}, [%4];"
        : "=r"(r[0]), "=r"(r[1]), "=r"(r[2]), "=r"(r[3]) : "r"(a));
}
__device__ __forceinline__ void mma16816(float* d, const uint32_t* a, uint32_t b0, uint32_t b1) {
    asm volatile("mma.sync.aligned.m16n8k16.row.col.f32.f16.f16.f32 "
        "{%0,%1,%2,%3}, {%4,%5,%6,%7}, {%8,%9}, {%0,%1,%2,%3};"
        : "+f"(d[0]), "+f"(d[1]), "+f"(d[2]), "+f"(d[3])
        : "r"(a[0]), "r"(a[1]), "r"(a[2]), "r"(a[3]), "r"(b0), "r"(b1));
}

// ---------------- device scratch ----------------
__device__ float g_alpha[8][5];
__device__ __half g_wA[WSZ];                  // [e][tap][oc][ic] fp16 folded 3x3/dil weights
__device__ __half g_w1[2 * 128 * 128];        // [st][oc][ic] fp16 1x1 weights
__device__ __half g_x[2L * 64 * 1024 * 128];  // [st][b][px][c] fp16 NHWC inputs (for 1x1 conv)
__device__ __half g_in[ISZ];                  // [st][b][py36*px36][c] fp16 states, zero halo
__device__ float g_max[5L * 64 * 128 * 1024]; // max3x3 per state, NCHW fp32

// ---------------- softmax ----------------
__global__ void softmax_kernel(const float* __restrict__ alphas) {
    int r = threadIdx.x;
    if (r < 8) {
        float m = -3.4e38f;
        #pragma unroll
        for (int j = 0; j < 5; j++) m = fmaxf(m, alphas[r * 5 + j]);
        float e[5], s = 0.f;
        #pragma unroll
        for (int j = 0; j < 5; j++) { e[j] = expf(alphas[r * 5 + j] - m); s += e[j]; }
        float inv = 1.f / s;
        #pragma unroll
        for (int j = 0; j < 5; j++) g_alpha[r][j] = e[j] * inv;
    }
}

// ---------------- weight prep: alpha-scale + identity/avg fold -> fp16 ----------------
__global__ void prep_w_kernel(const float* __restrict__ wc, const float* __restrict__ wd) {
    int idx = blockIdx.x * blockDim.x + threadIdx.x;
    if (idx >= WSZ) return;
    int ic = idx & 127;
    int oc = (idx >> 7) & 127;
    int r = idx >> 14;
    int tap = r % 18, e = r / 18;
    float v;
    if (tap < 9) {
        v = g_alpha[e][1] * wc[((e * 128 + oc) * 128 + ic) * 9 + tap];
        if (oc == ic) {
            v += g_alpha[e][3] * (1.f / 9.f);
            if (tap == 4) v += g_alpha[e][0];
        }
    } else {
        v = g_alpha[e][2] * wd[((e * 128 + oc) * 128 + ic) * 9 + tap - 9];
    }
    g_wA[idx] = __float2half_rn(v);
}

__global__ void prep_w1_kernel(const float* __restrict__ w0, const float* __restrict__ w1) {
    int idx = blockIdx.x * blockDim.x + threadIdx.x;
    if (idx >= 32768) return;
    const float* s = (idx < 16384) ? w0 : w1;
    g_w1[idx] = __float2half_rn(s[idx & 16383]);
}

// ---------------- input transpose: NCHW fp32 -> NHWC fp16 ----------------
__global__ __launch_bounds__(256) void in_tr_kernel(const float* __restrict__ in0,
                                                    const float* __restrict__ in1) {
    __shared__ __half s_tr[128][130];
    int t = threadIdx.x;
    int px0 = blockIdx.x * 128, b = blockIdx.y, st = blockIdx.z;
    const float* src = st ? in1 : in0;
    #pragma unroll
    for (int i = 0; i < 16; i++) {
        int idx = t + i * 256;
        int c = idx >> 5, f4 = idx & 31;
        float4 v = *(const float4*)(src + ((size_t)(b * 128 + c)) * 1024 + px0 + f4 * 4);
        s_tr[f4 * 4 + 0][c] = __float2half_rn(v.x);
        s_tr[f4 * 4 + 1][c] = __float2half_rn(v.y);
        s_tr[f4 * 4 + 2][c] = __float2half_rn(v.z);
        s_tr[f4 * 4 + 3][c] = __float2half_rn(v.w);
    }
    __syncthreads();
    #pragma unroll
    for (int k = 0; k < 8; k++) {
        int px = (t >> 4) + k * 16, ch = t & 15;
        const __half2* sp = (const __half2*)&s_tr[px][ch * 8];
        uint4 v;
        v.x = *(const uint32_t*)&sp[0]; v.y = *(const uint32_t*)&sp[1];
        v.z = *(const uint32_t*)&sp[2]; v.w = *(const uint32_t*)&sp[3];
        *(uint4*)(g_x + ((size_t)(st * 64 + b) * 1024 + px0 + px) * 128 + ch * 8) = v;
    }
}

// ---------------- 1x1 conv as fp16 GEMM ----------------
__global__ __launch_bounds__(256) void pre_gemm_kernel() {
    extern __shared__ char dsm[];
    int t = threadIdx.x;
    int pxg = blockIdx.x, b = blockIdx.y, st = blockIdx.z;
    uint32_t base = (s2u(dsm) + 1023u) & ~1023u;

    const int lane = t & 31, wid = t >> 5;
    const int wm = wid & 3, wn = wid >> 2;
    const int lrow = (lane & 7) + ((lane >> 3) & 1) * 8;
    const int chalf = lane >> 4;

    #pragma unroll
    for (int j = 0; j < 8; j++) {
        int idx = t + j * 256;
        int row = idx >> 4, c16 = idx & 15;
        cp16(base + (uint32_t)(row * 256 + ((c16 ^ (row & 7)) << 4)),
             g_w1 + (st << 14) + row * 128 + c16 * 8);
    }
    #pragma unroll
    for (int j = 0; j < 16; j++) {
        int idx = t + j * 256;
        int row = idx >> 4, c16 = idx & 15;
        cp16(base + 32768u + (uint32_t)(row * 256 + ((c16 ^ (row & 7)) << 4)),
             g_x + ((size_t)(st * 64 + b) * 1024 + pxg * 256 + row) * 128 + c16 * 8);
    }
    cp_commit();
    asm volatile("cp.async.wait_group 0;" ::: "memory");
    __syncthreads();

    float acc[2][16][4];
    #pragma unroll
    for (int mi = 0; mi < 2; mi++)
        #pragma unroll
        for (int ni = 0; ni < 16; ni++)
            #pragma unroll
            for (int j = 0; j < 4; j++) acc[mi][ni][j] = 0.f;

    #pragma unroll
    for (int kc = 0; kc < 8; kc++) {
        uint32_t af[2][4];
        #pragma unroll
        for (int mi = 0; mi < 2; mi++) {
            int row = wm * 32 + mi * 16 + lrow;
            ldx4(af[mi], base + (uint32_t)(row * 256 + (((2 * kc + chalf) ^ (row & 7)) << 4)));
        }
        #pragma unroll
        for (int pi = 0; pi < 8; pi++) {
            uint32_t bf[4];
            int row = wn * 128 + pi * 16 + lrow;
            ldx4(bf, base + 32768u +
                     (uint32_t)(row * 256 + (((2 * kc + chalf) ^ (row & 7)) << 4)));
            #pragma unroll
            for (int mi = 0; mi < 2; mi++) {
                mma16816(acc[mi][2 * pi],     af[mi], bf[0], bf[2]);
                mma16816(acc[mi][2 * pi + 1], af[mi], bf[1], bf[3]);
            }
        }
    }
    __syncthreads();

    __half* s_t = (__half*)(dsm + (base - s2u(dsm)));
    int tq = lane >> 2, tr = (lane & 3) * 2;
    #pragma unroll
    for (int mi = 0; mi < 2; mi++)
        #pragma unroll
        for (int h = 0; h < 2; h++) {
            int oc = wm * 32 + mi * 16 + tq + h * 8;
            #pragma unroll
            for (int ni = 0; ni < 16; ni++) {
                int px = wn * 128 + ni * 8 + tr;
                s_t[px * 136 + oc]       = __float2half_rn(acc[mi][ni][2 * h]);
                s_t[(px + 1) * 136 + oc] = __float2half_rn(acc[mi][ni][2 * h + 1]);
            }
        }
    __syncthreads();
    #pragma unroll
    for (int k = 0; k < 16; k++) {
        int px = (t >> 4) + k * 16, ch = t & 15;
        uint4 v = *(const uint4*)&s_t[px * 136 + ch * 8];
        int y = pxg * 8 + (px >> 5), xx = px & 31;
        *(uint4*)(g_in + ((size_t)(st * 64 + b) * 1296 + (y + 2) * 36 + xx + 2) * 128 + ch * 8) = v;
    }
}

// ---------------- separable 3x3 max pool ----------------
__device__ __forceinline__ void rowmax3(const __half* bp, int ry, int x, __half2* h,
                                        __half2 NINF) {
    if ((unsigned)ry < 32u) {
        __half2 m[4], l[4], r[4];
        *(uint4*)m = *(const uint4*)(bp + ((ry + 2) * 36 + x + 2) * 128);
        if (x > 0) *(uint4*)l = *(const uint4*)(bp + ((ry + 2) * 36 + x + 1) * 128);
        else { l[0] = l[1] = l[2] = l[3] = NINF; }
        if (x < 31) *(uint4*)r = *(const uint4*)(bp + ((ry + 2) * 36 + x + 3) * 128);
        else { r[0] = r[1] = r[2] = r[3] = NINF; }
        #pragma unroll
        for (int j = 0; j < 4; j++) h[j] = __hmax2(__hmax2(l[j], m[j]), r[j]);
    } else {
        h[0] = h[1] = h[2] = h[3] = NINF;
    }
}

__global__ __launch_bounds__(256) void max_kernel(int st0) {
    int t = threadIdx.x;
    int x = t & 31, cg = t >> 5;
    int b = blockIdx.y, y0 = blockIdx.x * 8;
    int st = st0 + blockIdx.z;
    const __half2 NINF = __half2half2(__ushort_as_half(0xFBFFu));
    #pragma unroll
    for (int hf = 0; hf < 2; hf++) {
        int c8 = (cg + hf * 8) * 8;
        const __half* bp = g_in + ((size_t)(st * 64 + b) * 1296) * 128 + c8;
        float* gmb = g_max + ((size_t)(st * 64 + b) * 128 + c8) * 1024 + x;
        __half2 a[4], bq[4], cq[4];
        rowmax3(bp, y0 - 1, x, a, NINF);
        rowmax3(bp, y0, x, bq, NINF);
        #pragma unroll
        for (int i = 0; i < 8; i++) {
            rowmax3(bp, y0 + i + 1, x, cq, NINF);
            int yo = (y0 + i) * 32;
            #pragma unroll
            for (int j = 0; j < 4; j++) {
                __half2 o = __hmax2(__hmax2(a[j], bq[j]), cq[j]);
                float2 f = __half22float2(o);
                gmb[(2 * j) * 1024 + yo]     = f.x;
                gmb[(2 * j + 1) * 1024 + yo] = f.y;
                a[j] = bq[j]; bq[j] = cq[j];
            }
        }
    }
}

// ---------------- mma.sync fp16 GEMM node kernel (act-resident smem) ----------------
// grid 256 (= 64 b * 4 rowgroups of 8 rows), 256 thr
// smem: act neighborhood 12x36 rows (110.6KB, loaded once per input) + 2x32KB weight ping-pong.
__global__ __launch_bounds__(256) void gemm_node_kernel(int stA, int stB, int e0, int e1,
                                                        int stOut, float* __restrict__ out) {
    extern __shared__ char dsm[];
    int t = threadIdx.x;
    int b = blockIdx.x >> 2;
    int y0r = (blockIdx.x & 3) * 8;

    uint32_t base = (s2u(dsm) + 1023u) & ~1023u;
    uint32_t actb = base;
    uint32_t wb = base + ACT_BYTES;

    const int lane = t & 31, wid = t >> 5;
    const int wm = wid & 3;
    const int wn = wid >> 2;
    const int lrow = (lane & 7) + ((lane >> 3) & 1) * 8;
    const int chalf = lane >> 4;

    // per-pi activation row base index (local 12x36 tile, center position)
    int nb[8];
    #pragma unroll
    for (int pi = 0; pi < 8; pi++) {
        int row = wn * 128 + pi * 16 + lrow;
        int yr = row >> 5, xx = row & 31;
        nb[pi] = (yr + 2) * 36 + (xx + 2);
    }

    float acc[2][16][4];
    #pragma unroll
    for (int mi = 0; mi < 2; mi++)
        #pragma unroll
        for (int ni = 0; ni < 16; ni++)
            #pragma unroll
            for (int j = 0; j < 4; j++) acc[mi][ni][j] = 0.f;

    #pragma unroll 1
    for (int inp = 0; inp < 2; inp++) {
        int e_ = inp ? e1 : e0;
        int st_ = inp ? stB : stA;
        const __half* bsrc = g_in + ((size_t)(st_ * 64 + b) * 1296) * 128;
        const __half* wbase_ = g_wA + ((size_t)(e_ * 18) << 14);

        __syncthreads();   // all warps done reading previous act tile
        // stage activation neighborhood: 432 rows x 256B (global rows y0r..y0r+11 linearized)
        #pragma unroll
        for (int j = 0; j < 27; j++) {
            int idx = t + j * 256;
            int n = idx >> 4, c16 = idx & 15;
            cp16(actb + (uint32_t)(n * 256 + ((c16 ^ (n & 7)) << 4)),
                 bsrc + (y0r * 36 + n) * 128 + c16 * 8);
        }
        // stage weights tap0 -> buf0
        #pragma unroll
        for (int j = 0; j < 8; j++) {
            int idx = t + j * 256;
            int row = idx >> 4, c16 = idx & 15;
            cp16(wb + (uint32_t)(row * 256 + ((c16 ^ (row & 7)) << 4)),
                 wbase_ + row * 128 + c16 * 8);
        }
        cp_commit();
        asm volatile("cp.async.wait_group 0;" ::: "memory");
        __syncthreads();

        #pragma unroll 1
        for (int tap = 0; tap < 18; tap++) {
            uint32_t wcur = wb + (uint32_t)((tap & 1) * 32768);
            if (tap < 17) {   // prefetch next weight tile
                const __half* wsn = wbase_ + ((size_t)(tap + 1) << 14);
                uint32_t wnx = wb + (uint32_t)(((tap + 1) & 1) * 32768);
                #pragma unroll
                for (int j = 0; j < 8; j++) {
                    int idx = t + j * 256;
                    int row = idx >> 4, c16 = idx & 15;
                    cp16(wnx + (uint32_t)(row * 256 + ((c16 ^ (row & 7)) << 4)),
                         wsn + row * 128 + c16 * 8);
                }
                cp_commit();
            }
            int dy, dx;
            if (tap < 9) { dy = tap / 3 - 1; dx = tap % 3 - 1; }
            else { int t2 = tap - 9; dy = (t2 / 3 - 1) * 2; dx = (t2 % 3 - 1) * 2; }
            int doff = dy * 36 + dx;

            #pragma unroll
            for (int kc = 0; kc < 8; kc++) {
                uint32_t af[2][4];
                #pragma unroll
                for (int mi = 0; mi < 2; mi++) {
                    int row = wm * 32 + mi * 16 + lrow;
                    ldx4(af[mi], wcur +
                         (uint32_t)(row * 256 + (((2 * kc + chalf) ^ (row & 7)) << 4)));
                }
                #pragma unroll
                for (int pi = 0; pi < 8; pi++) {
                    uint32_t bf[4];
                    int n = nb[pi] + doff;
                    ldx4(bf, actb +
                         (uint32_t)(n * 256 + (((2 * kc + chalf) ^ (n & 7)) << 4)));
                    #pragma unroll
                    for (int mi = 0; mi < 2; mi++) {
                        mma16816(acc[mi][2 * pi],     af[mi], bf[0], bf[2]);
                        mma16816(acc[mi][2 * pi + 1], af[mi], bf[1], bf[3]);
                    }
                }
            }
            if (tap < 17) {
                asm volatile("cp.async.wait_group 0;" ::: "memory");
                __syncthreads();
            }
        }
    }

    // epilogue: add max-pool terms, write fp32 out (+ fp16 state via smem transpose)
    __syncthreads();   // act tile reads complete before reuse as transpose buffer
    float a4A = g_alpha[e0][4], a4B = g_alpha[e1][4];
    __half* s_t = (__half*)(dsm + (actb - s2u(dsm)));
    int tq = lane >> 2;
    int tr = (lane & 3) * 2;
    #pragma unroll
    for (int mi = 0; mi < 2; mi++) {
        #pragma unroll
        for (int h = 0; h < 2; h++) {
            int oc = wm * 32 + mi * 16 + tq + h * 8;
            const float* mA = g_max + ((size_t)(stA * 64 + b) * 128 + oc) * 1024 + y0r * 32;
            const float* mB = g_max + ((size_t)(stB * 64 + b) * 128 + oc) * 1024 + y0r * 32;
            float* op = out + ((long)b * OUTC + oc) * HW + y0r * 32;
            #pragma unroll
            for (int ni = 0; ni < 16; ni++) {
                int px = wn * 128 + ni * 8 + tr;
                float v0 = acc[mi][ni][2 * h]     + a4A * mA[px]     + a4B * mB[px];
                float v1 = acc[mi][ni][2 * h + 1] + a4A * mA[px + 1] + a4B * mB[px + 1];
                *(float2*)&op[px] = make_float2(v0, v1);
                if (stOut >= 0) {
                    s_t[px * 136 + oc]       = __float2half_rn(v0);
                    s_t[(px + 1) * 136 + oc] = __float2half_rn(v1);
                }
            }
        }
    }
    if (stOut >= 0) {
        __syncthreads();
        #pragma unroll
        for (int k = 0; k < 16; k++) {
            int px = (t >> 4) + k * 16, ch = t & 15;
            uint4 v = *(const uint4*)&s_t[px * 136 + ch * 8];
            int y = y0r + (px >> 5), xx = px & 31;
            *(uint4*)(g_in + ((size_t)(stOut * 64 + b) * 1296 + (y + 2) * 36 + xx + 2) * 128
                      + ch * 8) = v;
        }
    }
}

// ---------------- skip copies ----------------
__global__ void copy_skip_kernel(const float* __restrict__ skip, float* __restrict__ out) {
    int idx = blockIdx.x * blockDim.x + threadIdx.x;
    float4 v = ((const float4*)skip)[idx];
    int hw4 = idx & 255;
    int c = (idx >> 8) & 127;
    int n = idx >> 15;
    ((float4*)out)[(long)n * (OUTC * HW / 4) + (512 + c) * (HW / 4) + hw4] = v;
    ((float4*)out)[(long)B * OUTC * HW / 4 + idx] = v;
}

// ---------------- launch ----------------
extern "C" void kernel_launch(void* const* d_in, const int* in_sizes, int n_in,
                              void* d_out, int out_size) {
    const float* input0  = (const float*)d_in[0];
    const float* input1  = (const float*)d_in[1];
    const float* skip    = (const float*)d_in[2];
    const float* w_pre0  = (const float*)d_in[3];
    const float* w_pre1  = (const float*)d_in[4];
    const float* w_conv3 = (const float*)d_in[5];
    const float* w_dil3  = (const float*)d_in[6];
    const float* alphas  = (const float*)d_in[7];
    float* out = (float*)d_out;

    softmax_kernel<<<1, 32>>>(alphas);
    prep_w_kernel<<<WSZ / 256, 256>>>(w_conv3, w_dil3);
    prep_w1_kernel<<<128, 256>>>(w_pre0, w_pre1);
    in_tr_kernel<<<dim3(8, 64, 2), 256>>>(input0, input1);

    const int psm = 98304 + 1024;
    cudaFuncSetAttribute(pre_gemm_kernel, cudaFuncAttributeMaxDynamicSharedMemorySize, psm);
    pre_gemm_kernel<<<dim3(4, 64, 2), 256, psm>>>();

    max_kernel<<<dim3(4, 64, 2), 256>>>(0);   // states 0,1

    const int gsm = ACT_BYTES + 2 * 32768 + 1024;
    cudaFuncSetAttribute(gemm_node_kernel, cudaFuncAttributeMaxDynamicSharedMemorySize, gsm);

    dim3 mgrid(4, 64, 1);
    gemm_node_kernel<<<256, 256, gsm>>>(0, 1, 0, 1, 2, out + 0 * C * HW);
    max_kernel<<<mgrid, 256>>>(2);
    gemm_node_kernel<<<256, 256, gsm>>>(1, 2, 2, 3, 3, out + 1 * C * HW);
    max_kernel<<<mgrid, 256>>>(3);
    gemm_node_kernel<<<256, 256, gsm>>>(2, 3, 4, 5, 4, out + 2 * C * HW);
    max_kernel<<<mgrid, 256>>>(4);
    gemm_node_kernel<<<256, 256, gsm>>>(3, 4, 6, 7, -1, out + 3 * C * HW);

    copy_skip_kernel<<<(B * C * HW / 4) / 256, 256>>>(skip, out);
}